// round 7
// baseline (speedup 1.0000x reference)
#include <cuda_runtime.h>

#define NPTS 65536
#define NS 16
#define NPAIR (NPTS*NS)
#define MF 1048576.0f
#define EPS 1e-5f

typedef unsigned long long ull;

__device__ __forceinline__ ull ffma2(ull a, ull b, ull c) {
    ull d; asm("fma.rn.f32x2 %0,%1,%2,%3;" : "=l"(d) : "l"(a), "l"(b), "l"(c)); return d;
}
__device__ __forceinline__ ull fmul2(ull a, ull b) {
    ull d; asm("mul.rn.f32x2 %0,%1,%2;" : "=l"(d) : "l"(a), "l"(b)); return d;
}
__device__ __forceinline__ ull fadd2(ull a, ull b) {
    ull d; asm("add.rn.f32x2 %0,%1,%2;" : "=l"(d) : "l"(a), "l"(b)); return d;
}
__device__ __forceinline__ ull pack2(float lo, float hi) {
    ull d; asm("mov.b64 %0,{%1,%2};" : "=l"(d) : "f"(lo), "f"(hi)); return d;
}
__device__ __forceinline__ void unpack2(ull v, float& lo, float& hi) {
    asm("mov.b64 {%0,%1},%2;" : "=f"(lo), "=f"(hi) : "l"(v));
}

// ---------------- scratch ----------------
__device__ float  g_xq[NPTS*64];
__device__ float  g_xk[NPTS*64];
__device__ float  g_xv[NPTS*64];
__device__ float4 g_prh4[NPAIR];   // {h0,h1,h2,0} per pair
__device__ float  g_w1[NPAIR*8];
__device__ float  g_accP[6];
__device__ float  g_accW[128];
__device__ float  g_accU[16];

__global__ void k_zero() {
    int t = threadIdx.x;
    if (t < 6)   g_accP[t] = 0.f;
    if (t < 128) g_accW[t] = 0.f;
    if (t < 16)  g_accU[t] = 0.f;
}

// ---------------- K1: qkv GEMM (64 pts/block) + pr1 BN stats ----------------
__global__ void __launch_bounds__(256) k1(
                   const float* __restrict__ x, const float* __restrict__ p,
                   const int* __restrict__ idx,
                   const float* __restrict__ Wq, const float* __restrict__ bq,
                   const float* __restrict__ Wk, const float* __restrict__ bk,
                   const float* __restrict__ Wv, const float* __restrict__ bv,
                   const float* __restrict__ Wp1, const float* __restrict__ bp1)
{
    extern __shared__ float sm[];
    float4* ws4  = (float4*)sm;            // [64][48] float4
    float*  xs   = sm + 64*48*4;           // [64][68]
    float4* bsm4 = (float4*)(xs + 64*68);  // [48]
    int tid = threadIdx.x;
    int base = blockIdx.x * 64;

    for (int i = tid; i < 64*48; i += 256) {
        int k = i / 48, r = i - k*48;
        int seg = r >> 4, tx = r & 15;
        const float4* src = (seg == 0) ? (const float4*)Wq :
                            (seg == 1) ? (const float4*)Wk : (const float4*)Wv;
        ws4[i] = src[k*16 + tx];
    }
    {
        float4* xs4 = (float4*)xs;
        for (int i = tid; i < 64*16; i += 256) {
            int pt = i >> 4, kk = i & 15;
            xs4[pt*17 + kk] = ((const float4*)x)[(base + pt)*16 + kk];
        }
    }
    if (tid < 48) {
        int seg = tid >> 4, tx = tid & 15;
        const float4* src = (seg == 0) ? (const float4*)bq :
                            (seg == 1) ? (const float4*)bk : (const float4*)bv;
        bsm4[tid] = src[tx];
    }
    __syncthreads();

    int tx = tid & 15, ty = tid >> 4;
    ulonglong2 acc[3][4];
    #pragma unroll
    for (int s = 0; s < 3; s++) {
        ulonglong2 b = ((ulonglong2*)bsm4)[s*16 + tx];
        #pragma unroll
        for (int r = 0; r < 4; r++) acc[s][r] = b;
    }

    #pragma unroll 4
    for (int kq = 0; kq < 16; kq++) {
        float4 aq[4];
        #pragma unroll
        for (int r = 0; r < 4; r++) aq[r] = *(float4*)&xs[(ty*4 + r)*68 + kq*4];
        #pragma unroll
        for (int e = 0; e < 4; e++) {
            int k = kq*4 + e;
            ull ap[4];
            #pragma unroll
            for (int r = 0; r < 4; r++) {
                float av = ((float*)&aq[r])[e];
                ap[r] = pack2(av, av);
            }
            #pragma unroll
            for (int s = 0; s < 3; s++) {
                ulonglong2 w2 = *(ulonglong2*)&ws4[k*48 + s*16 + tx];
                #pragma unroll
                for (int r = 0; r < 4; r++) {
                    acc[s][r].x = ffma2(ap[r], w2.x, acc[s][r].x);
                    acc[s][r].y = ffma2(ap[r], w2.y, acc[s][r].y);
                }
            }
        }
    }

    #pragma unroll
    for (int r = 0; r < 4; r++) {
        int pt = base + ty*4 + r;
        ((ulonglong2*)&g_xq[pt*64])[tx] = acc[0][r];
        ((ulonglong2*)&g_xk[pt*64])[tx] = acc[1][r];
        ((ulonglong2*)&g_xv[pt*64])[tx] = acc[2][r];
    }

    // ---- pr1 stats over this block's 1024 pairs ----
    float w00 = Wp1[0], w01 = Wp1[1], w02 = Wp1[2];
    float w10 = Wp1[3], w11 = Wp1[4], w12 = Wp1[5];
    float w20 = Wp1[6], w21 = Wp1[7], w22 = Wp1[8];
    float c0 = bp1[0], c1 = bp1[1], c2 = bp1[2];
    float s0=0,s1=0,s2=0,q0=0,q1=0,q2=0;
    for (int t = tid; t < 1024; t += 256) {
        int n = base + (t >> 4);
        int g = idx[n*NS + (t & 15)];
        float r0 = p[g*3+0] - p[n*3+0];
        float r1 = p[g*3+1] - p[n*3+1];
        float r2 = p[g*3+2] - p[n*3+2];
        float v0 = c0 + r0*w00 + r1*w10 + r2*w20;
        float v1 = c1 + r0*w01 + r1*w11 + r2*w21;
        float v2 = c2 + r0*w02 + r1*w12 + r2*w22;
        s0 += v0; s1 += v1; s2 += v2;
        q0 += v0*v0; q1 += v1*v1; q2 += v2*v2;
    }
    #pragma unroll
    for (int off = 16; off; off >>= 1) {
        s0 += __shfl_xor_sync(0xffffffffu, s0, off);
        s1 += __shfl_xor_sync(0xffffffffu, s1, off);
        s2 += __shfl_xor_sync(0xffffffffu, s2, off);
        q0 += __shfl_xor_sync(0xffffffffu, q0, off);
        q1 += __shfl_xor_sync(0xffffffffu, q1, off);
        q2 += __shfl_xor_sync(0xffffffffu, q2, off);
    }
    __syncthreads();
    float* red = sm;
    int lane = tid & 31, wrp = tid >> 5;
    if (lane == 0) {
        red[wrp*6+0] = s0; red[wrp*6+1] = s1; red[wrp*6+2] = s2;
        red[wrp*6+3] = q0; red[wrp*6+4] = q1; red[wrp*6+5] = q2;
    }
    __syncthreads();
    if (tid < 6) {
        float t2 = 0.f;
        #pragma unroll
        for (int w = 0; w < 8; w++) t2 += red[w*6 + tid];
        atomicAdd(&g_accP[tid], t2);
    }
}

// ---------------- K2: pr_hat + w-channel BN stats ----------------
__global__ void __launch_bounds__(256) k2(
                   const float* __restrict__ p, const int* __restrict__ idx,
                   const float* __restrict__ Wp1, const float* __restrict__ bp1,
                   const float* __restrict__ gp, const float* __restrict__ bpbn,
                   const float* __restrict__ Wp2, const float* __restrict__ bp2)
{
    __shared__ float4 prh4[1024];
    __shared__ float  xqn[64*64];
    __shared__ int    gixs[1024];
    __shared__ float  sred[1024];
    int tid = threadIdx.x;
    int pair0 = blockIdx.x * 1024;
    int pbase = pair0 >> 4;

    for (int i = tid; i < 1024; i += 256) gixs[i] = idx[pair0 + i];
    for (int i = tid; i < 4096; i += 256) xqn[i] = -g_xq[pbase*64 + i];

    float scP[3], shP[3];
    #pragma unroll
    for (int c = 0; c < 3; c++) {
        float mean = g_accP[c] / MF;
        float var  = g_accP[3+c] / MF - mean*mean;
        float sc   = gp[c] * rsqrtf(var + EPS);
        scP[c] = sc;
        shP[c] = bpbn[c] - mean*sc;
    }
    float w00 = Wp1[0], w01 = Wp1[1], w02 = Wp1[2];
    float w10 = Wp1[3], w11 = Wp1[4], w12 = Wp1[5];
    float w20 = Wp1[6], w21 = Wp1[7], w22 = Wp1[8];
    float c0 = bp1[0], c1 = bp1[1], c2 = bp1[2];
    __syncthreads();

    #pragma unroll
    for (int kk = 0; kk < 4; kk++) {
        int t = tid + kk*256;
        int n = pbase + (t >> 4);
        int g = gixs[t];
        float r0 = p[g*3+0] - p[n*3+0];
        float r1 = p[g*3+1] - p[n*3+1];
        float r2 = p[g*3+2] - p[n*3+2];
        float v0 = c0 + r0*w00 + r1*w10 + r2*w20;
        float v1 = c1 + r0*w01 + r1*w11 + r2*w21;
        float v2 = c2 + r0*w02 + r1*w12 + r2*w22;
        float h0 = fmaxf(v0*scP[0] + shP[0], 0.f);
        float h1 = fmaxf(v1*scP[1] + shP[1], 0.f);
        float h2 = fmaxf(v2*scP[2] + shP[2], 0.f);
        float4 h = make_float4(h0, h1, h2, 0.f);
        prh4[t] = h;
        g_prh4[pair0 + t] = h;
    }
    __syncthreads();

    int cq = (tid & 15) * 4;
    float4 A0q = __ldg((const float4*)&Wp2[cq]);
    float4 A1q = __ldg((const float4*)&Wp2[64 + cq]);
    float4 A2q = __ldg((const float4*)&Wp2[128 + cq]);
    float4 Bq  = __ldg((const float4*)&bp2[cq]);
    ulonglong2 A0u = *(ulonglong2*)&A0q, A1u = *(ulonglong2*)&A1q;
    ulonglong2 A2u = *(ulonglong2*)&A2q, Bu  = *(ulonglong2*)&Bq;

    ull s_lo = 0, s_hi = 0, ss_lo = 0, ss_hi = 0;
    int pl = tid >> 4;
    #pragma unroll 4
    for (int k = 0; k < 64; k++) {
        int t = pl + 16*k;
        int g = gixs[t];
        float4 xk4 = __ldg((const float4*)&g_xk[(size_t)g*64 + cq]);
        float4 h4 = prh4[t];
        ull h0p = pack2(h4.x, h4.x), h1p = pack2(h4.y, h4.y), h2p = pack2(h4.z, h4.z);
        ulonglong2 xku = *(ulonglong2*)&xk4;
        ulonglong2 xqu = *(ulonglong2*)&xqn[(t >> 4)*64 + cq];
        ull t_lo = ffma2(h2p, A2u.x, ffma2(h1p, A1u.x, ffma2(h0p, A0u.x, Bu.x)));
        ull t_hi = ffma2(h2p, A2u.y, ffma2(h1p, A1u.y, ffma2(h0p, A0u.y, Bu.y)));
        ull w_lo = fadd2(xku.x, fadd2(xqu.x, t_lo));
        ull w_hi = fadd2(xku.y, fadd2(xqu.y, t_hi));
        s_lo = fadd2(s_lo, w_lo); s_hi = fadd2(s_hi, w_hi);
        ss_lo = ffma2(w_lo, w_lo, ss_lo); ss_hi = ffma2(w_hi, w_hi, ss_hi);
    }

    float v[8];
    unpack2(s_lo, v[0], v[1]); unpack2(s_hi, v[2], v[3]);
    unpack2(ss_lo, v[4], v[5]); unpack2(ss_hi, v[6], v[7]);
    #pragma unroll
    for (int i = 0; i < 8; i++) v[i] += __shfl_xor_sync(0xffffffffu, v[i], 16);
    int lane = tid & 31, wrp = tid >> 5;
    if (lane < 16) {
        #pragma unroll
        for (int i = 0; i < 8; i++) sred[lane*64 + wrp*8 + i] = v[i];
    }
    __syncthreads();
    if (tid < 128) {
        int q = tid >> 3, vi = tid & 7;
        float s = 0.f;
        #pragma unroll
        for (int w = 0; w < 8; w++) s += sred[q*64 + w*8 + vi];
        int gi = (vi < 4) ? (q*4 + vi) : (64 + q*4 + vi - 4);
        atomicAdd(&g_accW[gi], s);
    }
}

// ---------------- K3: 16 lanes/pair, reg tables, depth-1 software pipeline ----------------
// grid 2048, block 256, 3 blocks/SM: 512 pairs (32 points) per block
__global__ void __launch_bounds__(256, 3) k3(
                   const int* __restrict__ idx,
                   const float* __restrict__ Wp2, const float* __restrict__ bp2,
                   const float* __restrict__ gw1, const float* __restrict__ bw1bn,
                   const float* __restrict__ Ww1, const float* __restrict__ bw1)
{
    __shared__ float xqn[32*64];     // -xq * sc
    __shared__ int   gixs[512];
    __shared__ float sS[64];
    __shared__ float wred[8*16];
    int tid = threadIdx.x;
    int lane = tid & 31, wrp = tid >> 5;
    int pair0 = blockIdx.x * 512;
    int pbase = pair0 >> 4;
    int cq = (tid & 15) * 4;
    int slot = tid >> 4;
    int P = (lane >> 2) & 3;

    if (tid < 64) {
        int c = tid;
        float mean = g_accW[c] / MF;
        float var  = g_accW[64 + c] / MF - mean*mean;
        sS[c] = gw1[c] * rsqrtf(var + EPS);
    }
    for (int i = tid; i < 512; i += 256) gixs[i] = idx[pair0 + i];

    ull A0u[2], A1u[2], A2u[2], Bu[2], Su[2];
    {
        float a0[4], a1[4], a2[4], bb[4], sv[4];
        #pragma unroll
        for (int e = 0; e < 4; e++) {
            int c = cq + e;
            float mean = g_accW[c] / MF;
            float var  = g_accW[64 + c] / MF - mean*mean;
            float sc   = gw1[c] * rsqrtf(var + EPS);
            float sh   = bw1bn[c] - mean*sc;
            sv[e] = sc;
            a0[e] = Wp2[c]*sc; a1[e] = Wp2[64+c]*sc; a2[e] = Wp2[128+c]*sc;
            bb[e] = bp2[c]*sc + sh;
        }
        A0u[0] = pack2(a0[0], a0[1]); A0u[1] = pack2(a0[2], a0[3]);
        A1u[0] = pack2(a1[0], a1[1]); A1u[1] = pack2(a1[2], a1[3]);
        A2u[0] = pack2(a2[0], a2[1]); A2u[1] = pack2(a2[2], a2[3]);
        Bu[0]  = pack2(bb[0], bb[1]); Bu[1]  = pack2(bb[2], bb[3]);
        Su[0]  = pack2(sv[0], sv[1]); Su[1]  = pack2(sv[2], sv[3]);
    }

    ull Wr[4][4];
    #pragma unroll
    for (int e = 0; e < 4; e++)
        #pragma unroll
        for (int s = 0; s < 4; s++)
            Wr[e][s] = __ldg((const ull*)Ww1 + (cq + e)*4 + (P ^ s));
    ull biasu = __ldg((const ull*)bw1 + P);
    __syncthreads();

    for (int i = tid; i < 2048; i += 256)
        xqn[i] = -g_xq[(size_t)pbase*64 + i] * sS[i & 63];
    __syncthreads();

    ull stS = 0, stQ = 0;

    // ---- pipeline prologue: load iteration 0 ----
    float4 h_cur = __ldg(&g_prh4[pair0 + slot]);
    ulonglong2 xk_cur;
    {
        int g0 = gixs[slot];
        xk_cur = __ldg((const ulonglong2*)&g_xk[(size_t)g0*64 + cq]);
    }

    #pragma unroll 1
    for (int k = 0; k < 32; k++) {
        int li = slot + (k << 4);
        int pair = pair0 + li;

        // prefetch next iteration's gather
        float4 h_n = h_cur;
        ulonglong2 xk_n = xk_cur;
        if (k < 31) {
            int li_n = li + 16;
            int g_n = gixs[li_n];
            h_n = __ldg(&g_prh4[pair0 + li_n]);
            xk_n = __ldg((const ulonglong2*)&g_xk[(size_t)g_n*64 + cq]);
        }

        ulonglong2 xqu = *(const ulonglong2*)&xqn[(k << 6) + cq];

        ull h0p = pack2(h_cur.x, h_cur.x), h1p = pack2(h_cur.y, h_cur.y), h2p = pack2(h_cur.z, h_cur.z);
        ull r_lo = ffma2(h2p, A2u[0], ffma2(h1p, A1u[0], ffma2(h0p, A0u[0], Bu[0])));
        ull r_hi = ffma2(h2p, A2u[1], ffma2(h1p, A1u[1], ffma2(h0p, A0u[1], Bu[1])));
        ull w_lo = ffma2(xk_cur.x, Su[0], fadd2(xqu.x, r_lo));
        ull w_hi = ffma2(xk_cur.y, Su[1], fadd2(xqu.y, r_hi));
        float w0, w1, w2, w3;
        unpack2(w_lo, w0, w1); unpack2(w_hi, w2, w3);
        float m0 = fmaxf(w0, 0.f), m1 = fmaxf(w1, 0.f);
        float m2 = fmaxf(w2, 0.f), m3 = fmaxf(w3, 0.f);
        ull wp0 = pack2(m0, m0), wp1 = pack2(m1, m1);
        ull wp2_ = pack2(m2, m2), wp3 = pack2(m3, m3);

        ull a0 = fmul2(wp0, Wr[0][0]);
        ull a1 = fmul2(wp0, Wr[0][1]);
        ull a2 = fmul2(wp0, Wr[0][2]);
        ull a3 = fmul2(wp0, Wr[0][3]);
        a0 = ffma2(wp1, Wr[1][0], a0); a1 = ffma2(wp1, Wr[1][1], a1);
        a2 = ffma2(wp1, Wr[1][2], a2); a3 = ffma2(wp1, Wr[1][3], a3);
        a0 = ffma2(wp2_, Wr[2][0], a0); a1 = ffma2(wp2_, Wr[2][1], a1);
        a2 = ffma2(wp2_, Wr[2][2], a2); a3 = ffma2(wp2_, Wr[2][3], a3);
        a0 = ffma2(wp3, Wr[3][0], a0); a1 = ffma2(wp3, Wr[3][1], a1);
        a2 = ffma2(wp3, Wr[3][2], a2); a3 = ffma2(wp3, Wr[3][3], a3);

        // reduce-scatter over the 16-lane pair group
        a0 = fadd2(a0, __shfl_xor_sync(0xffffffffu, a2, 8));
        a1 = fadd2(a1, __shfl_xor_sync(0xffffffffu, a3, 8));
        a0 = fadd2(a0, __shfl_xor_sync(0xffffffffu, a1, 4));
        a0 = fadd2(a0, __shfl_xor_sync(0xffffffffu, a0, 2));
        a0 = fadd2(a0, __shfl_xor_sync(0xffffffffu, a0, 1));
        a0 = fadd2(a0, biasu);

        if ((lane & 3) == 0)
            *((ull*)g_w1 + (size_t)pair*4 + P) = a0;

        stS = fadd2(stS, a0);
        stQ = ffma2(a0, a0, stQ);

        h_cur = h_n;
        xk_cur = xk_n;
    }

    stS = fadd2(stS, __shfl_xor_sync(0xffffffffu, stS, 16));
    stQ = fadd2(stQ, __shfl_xor_sync(0xffffffffu, stQ, 16));
    if (lane < 16 && (lane & 3) == 0) {
        float s0, s1, q0, q1;
        unpack2(stS, s0, s1); unpack2(stQ, q0, q1);
        wred[wrp*16 + 2*P]     = s0;
        wred[wrp*16 + 2*P + 1] = s1;
        wred[wrp*16 + 8 + 2*P]     = q0;
        wred[wrp*16 + 8 + 2*P + 1] = q1;
    }
    __syncthreads();
    if (tid < 16) {
        float s = 0.f;
        #pragma unroll
        for (int w = 0; w < 8; w++) s += wred[w*16 + tid];
        atomicAdd(&g_accU[tid], s);
    }
}

// ---------------- K4: bn2+relu -> @Ww2 -> softmax(ns) -> aggregate ----------------
__global__ void __launch_bounds__(256) k4(
                   const int* __restrict__ idx,
                   const float* __restrict__ Wp2, const float* __restrict__ bp2,
                   const float* __restrict__ gw2, const float* __restrict__ bw2bn,
                   const float* __restrict__ Ww2, const float* __restrict__ bw2,
                   float* __restrict__ out)
{
    __shared__ float w1s[4][128];
    __shared__ float hs[4][128];
    __shared__ float w2s[4][128];
    __shared__ float prs[4][48];
    __shared__ int   gix4[4][16];
    __shared__ float wp2s[192], bp2s[64], wws[64], bws[8];
    int tid = threadIdx.x;
    int sub = tid >> 6, ct = tid & 63;
    int n = blockIdx.x*4 + sub;

    for (int i = tid; i < 192; i += 256) wp2s[i] = Wp2[i];
    if (tid < 64) { bp2s[tid] = bp2[tid]; wws[tid] = Ww2[tid]; }
    if (tid < 8)  bws[tid] = bw2[tid];

    w1s[sub][ct]      = g_w1[n*128 + ct];
    w1s[sub][ct + 64] = g_w1[n*128 + ct + 64];
    if (ct < 16) {
        gix4[sub][ct] = idx[n*16 + ct];
        float4 h = g_prh4[n*16 + ct];
        prs[sub][ct] = h.x; prs[sub][16 + ct] = h.y; prs[sub][32 + ct] = h.z;
    }

    int u = ct & 7;
    float mean = g_accU[u] / MF;
    float var  = g_accU[8 + u] / MF - mean*mean;
    float sc2  = gw2[u] * rsqrtf(var + EPS);
    float sh2  = bw2bn[u] - mean*sc2;
    __syncthreads();

    hs[sub][ct]      = fmaxf(w1s[sub][ct]*sc2 + sh2, 0.f);
    hs[sub][ct + 64] = fmaxf(w1s[sub][ct + 64]*sc2 + sh2, 0.f);
    __syncthreads();

    #pragma unroll
    for (int o = ct; o < 128; o += 64) {
        int j = o >> 3, t = o & 7;
        float v = bws[t];
        #pragma unroll
        for (int uu = 0; uu < 8; uu++) v += hs[sub][j*8 + uu] * wws[uu*8 + t];
        w2s[sub][o] = v;
    }
    __syncthreads();

    if (ct < 8) {
        int t = ct;
        float m = -1e30f;
        #pragma unroll
        for (int j = 0; j < 16; j++) m = fmaxf(m, w2s[sub][j*8 + t]);
        float e[16], ssum = 0.f;
        #pragma unroll
        for (int j = 0; j < 16; j++) { e[j] = __expf(w2s[sub][j*8 + t] - m); ssum += e[j]; }
        float inv = 1.f / ssum;
        #pragma unroll
        for (int j = 0; j < 16; j++) w2s[sub][j*8 + t] = e[j] * inv;
    }
    __syncthreads();

    int t = ct & 7;
    float a0 = wp2s[ct], a1 = wp2s[64 + ct], a2 = wp2s[128 + ct], bb = bp2s[ct];
    float acc = 0.f;
    #pragma unroll
    for (int j = 0; j < 16; j++) {
        int g = gix4[sub][j];
        float v = g_xv[(size_t)g*64 + ct];
        float pr = fmaf(prs[sub][32 + j], a2, fmaf(prs[sub][16 + j], a1, fmaf(prs[sub][j], a0, bb)));
        acc += (v + pr) * w2s[sub][j*8 + t];
    }
    out[n*64 + ct] = acc;
}

// ---------------- launch ----------------
extern "C" void kernel_launch(void* const* d_in, const int* in_sizes, int n_in,
                              void* d_out, int out_size)
{
    const float* p    = (const float*)d_in[0];
    const float* x    = (const float*)d_in[1];
    const int*   idx  = (const int*)d_in[2];
    const float* Wq   = (const float*)d_in[3];
    const float* bq   = (const float*)d_in[4];
    const float* Wk   = (const float*)d_in[5];
    const float* bk   = (const float*)d_in[6];
    const float* Wv   = (const float*)d_in[7];
    const float* bv   = (const float*)d_in[8];
    const float* Wp1  = (const float*)d_in[9];
    const float* bp1  = (const float*)d_in[10];
    const float* gp   = (const float*)d_in[11];
    const float* bpbn = (const float*)d_in[12];
    const float* Wp2  = (const float*)d_in[13];
    const float* bp2  = (const float*)d_in[14];
    const float* gw1  = (const float*)d_in[15];
    const float* bw1bn= (const float*)d_in[16];
    const float* Ww1  = (const float*)d_in[17];
    const float* bw1  = (const float*)d_in[18];
    const float* gw2  = (const float*)d_in[19];
    const float* bw2bn= (const float*)d_in[20];
    const float* Ww2  = (const float*)d_in[21];
    const float* bw2  = (const float*)d_in[22];
    float* out = (float*)d_out;

    size_t smem1 = (size_t)(64*48*4 + 64*68 + 48*4) * 4;  // ~66KB
    cudaFuncSetAttribute(k1, cudaFuncAttributeMaxDynamicSharedMemorySize, (int)smem1);

    k_zero<<<1, 256>>>();
    k1<<<1024, 256, smem1>>>(x, p, idx, Wq, bq, Wk, bk, Wv, bv, Wp1, bp1);
    k2<<<1024, 256>>>(p, idx, Wp1, bp1, gp, bpbn, Wp2, bp2);
    k3<<<2048, 256>>>(idx, Wp2, bp2, gw1, bw1bn, Ww1, bw1);
    k4<<<16384, 256>>>(idx, Wp2, bp2, gw2, bw2bn, Ww2, bw2, out);
}

// round 8
// speedup vs baseline: 1.0224x; 1.0224x over previous
#include <cuda_runtime.h>

#define NPTS 65536
#define NS 16
#define NPAIR (NPTS*NS)
#define MF 1048576.0f
#define EPS 1e-5f

typedef unsigned long long ull;

__device__ __forceinline__ ull ffma2(ull a, ull b, ull c) {
    ull d; asm("fma.rn.f32x2 %0,%1,%2,%3;" : "=l"(d) : "l"(a), "l"(b), "l"(c)); return d;
}
__device__ __forceinline__ ull fmul2(ull a, ull b) {
    ull d; asm("mul.rn.f32x2 %0,%1,%2;" : "=l"(d) : "l"(a), "l"(b)); return d;
}
__device__ __forceinline__ ull fadd2(ull a, ull b) {
    ull d; asm("add.rn.f32x2 %0,%1,%2;" : "=l"(d) : "l"(a), "l"(b)); return d;
}
__device__ __forceinline__ ull pack2(float lo, float hi) {
    ull d; asm("mov.b64 %0,{%1,%2};" : "=l"(d) : "f"(lo), "f"(hi)); return d;
}
__device__ __forceinline__ void unpack2(ull v, float& lo, float& hi) {
    asm("mov.b64 {%0,%1},%2;" : "=f"(lo), "=f"(hi) : "l"(v));
}

// ---------------- scratch ----------------
__device__ float  g_xq[NPTS*64];
__device__ float  g_xk[NPTS*64];
__device__ float  g_xv[NPTS*64];
__device__ float4 g_prh4[NPAIR];   // {h0,h1,h2,0} per pair
__device__ float  g_w1[NPAIR*8];
__device__ float  g_accP[6];
__device__ float  g_accW[128];
__device__ float  g_accU[16];

__global__ void k_zero() {
    int t = threadIdx.x;
    if (t < 6)   g_accP[t] = 0.f;
    if (t < 128) g_accW[t] = 0.f;
    if (t < 16)  g_accU[t] = 0.f;
}

// ---------------- K1: qkv GEMM (64 pts/block) + pr1 BN stats ----------------
__global__ void __launch_bounds__(256) k1(
                   const float* __restrict__ x, const float* __restrict__ p,
                   const int* __restrict__ idx,
                   const float* __restrict__ Wq, const float* __restrict__ bq,
                   const float* __restrict__ Wk, const float* __restrict__ bk,
                   const float* __restrict__ Wv, const float* __restrict__ bv,
                   const float* __restrict__ Wp1, const float* __restrict__ bp1)
{
    extern __shared__ float sm[];
    float4* ws4  = (float4*)sm;            // [64][48] float4
    float*  xs   = sm + 64*48*4;           // [64][68]
    float4* bsm4 = (float4*)(xs + 64*68);  // [48]
    int tid = threadIdx.x;
    int base = blockIdx.x * 64;

    for (int i = tid; i < 64*48; i += 256) {
        int k = i / 48, r = i - k*48;
        int seg = r >> 4, tx = r & 15;
        const float4* src = (seg == 0) ? (const float4*)Wq :
                            (seg == 1) ? (const float4*)Wk : (const float4*)Wv;
        ws4[i] = src[k*16 + tx];
    }
    {
        float4* xs4 = (float4*)xs;
        for (int i = tid; i < 64*16; i += 256) {
            int pt = i >> 4, kk = i & 15;
            xs4[pt*17 + kk] = ((const float4*)x)[(base + pt)*16 + kk];
        }
    }
    if (tid < 48) {
        int seg = tid >> 4, tx = tid & 15;
        const float4* src = (seg == 0) ? (const float4*)bq :
                            (seg == 1) ? (const float4*)bk : (const float4*)bv;
        bsm4[tid] = src[tx];
    }
    __syncthreads();

    int tx = tid & 15, ty = tid >> 4;
    ulonglong2 acc[3][4];
    #pragma unroll
    for (int s = 0; s < 3; s++) {
        ulonglong2 b = ((ulonglong2*)bsm4)[s*16 + tx];
        #pragma unroll
        for (int r = 0; r < 4; r++) acc[s][r] = b;
    }

    #pragma unroll 4
    for (int kq = 0; kq < 16; kq++) {
        float4 aq[4];
        #pragma unroll
        for (int r = 0; r < 4; r++) aq[r] = *(float4*)&xs[(ty*4 + r)*68 + kq*4];
        #pragma unroll
        for (int e = 0; e < 4; e++) {
            int k = kq*4 + e;
            ull ap[4];
            #pragma unroll
            for (int r = 0; r < 4; r++) {
                float av = ((float*)&aq[r])[e];
                ap[r] = pack2(av, av);
            }
            #pragma unroll
            for (int s = 0; s < 3; s++) {
                ulonglong2 w2 = *(ulonglong2*)&ws4[k*48 + s*16 + tx];
                #pragma unroll
                for (int r = 0; r < 4; r++) {
                    acc[s][r].x = ffma2(ap[r], w2.x, acc[s][r].x);
                    acc[s][r].y = ffma2(ap[r], w2.y, acc[s][r].y);
                }
            }
        }
    }

    #pragma unroll
    for (int r = 0; r < 4; r++) {
        int pt = base + ty*4 + r;
        ((ulonglong2*)&g_xq[pt*64])[tx] = acc[0][r];
        ((ulonglong2*)&g_xk[pt*64])[tx] = acc[1][r];
        ((ulonglong2*)&g_xv[pt*64])[tx] = acc[2][r];
    }

    // ---- pr1 stats over this block's 1024 pairs ----
    float w00 = Wp1[0], w01 = Wp1[1], w02 = Wp1[2];
    float w10 = Wp1[3], w11 = Wp1[4], w12 = Wp1[5];
    float w20 = Wp1[6], w21 = Wp1[7], w22 = Wp1[8];
    float c0 = bp1[0], c1 = bp1[1], c2 = bp1[2];
    float s0=0,s1=0,s2=0,q0=0,q1=0,q2=0;
    for (int t = tid; t < 1024; t += 256) {
        int n = base + (t >> 4);
        int g = idx[n*NS + (t & 15)];
        float r0 = p[g*3+0] - p[n*3+0];
        float r1 = p[g*3+1] - p[n*3+1];
        float r2 = p[g*3+2] - p[n*3+2];
        float v0 = c0 + r0*w00 + r1*w10 + r2*w20;
        float v1 = c1 + r0*w01 + r1*w11 + r2*w21;
        float v2 = c2 + r0*w02 + r1*w12 + r2*w22;
        s0 += v0; s1 += v1; s2 += v2;
        q0 += v0*v0; q1 += v1*v1; q2 += v2*v2;
    }
    #pragma unroll
    for (int off = 16; off; off >>= 1) {
        s0 += __shfl_xor_sync(0xffffffffu, s0, off);
        s1 += __shfl_xor_sync(0xffffffffu, s1, off);
        s2 += __shfl_xor_sync(0xffffffffu, s2, off);
        q0 += __shfl_xor_sync(0xffffffffu, q0, off);
        q1 += __shfl_xor_sync(0xffffffffu, q1, off);
        q2 += __shfl_xor_sync(0xffffffffu, q2, off);
    }
    __syncthreads();
    float* red = sm;
    int lane = tid & 31, wrp = tid >> 5;
    if (lane == 0) {
        red[wrp*6+0] = s0; red[wrp*6+1] = s1; red[wrp*6+2] = s2;
        red[wrp*6+3] = q0; red[wrp*6+4] = q1; red[wrp*6+5] = q2;
    }
    __syncthreads();
    if (tid < 6) {
        float t2 = 0.f;
        #pragma unroll
        for (int w = 0; w < 8; w++) t2 += red[w*6 + tid];
        atomicAdd(&g_accP[tid], t2);
    }
}

// ---------------- K2: pr_hat + w-channel BN stats ----------------
__global__ void __launch_bounds__(256) k2(
                   const float* __restrict__ p, const int* __restrict__ idx,
                   const float* __restrict__ Wp1, const float* __restrict__ bp1,
                   const float* __restrict__ gp, const float* __restrict__ bpbn,
                   const float* __restrict__ Wp2, const float* __restrict__ bp2)
{
    __shared__ float4 prh4[1024];
    __shared__ float  xqn[64*64];
    __shared__ int    gixs[1024];
    __shared__ int    goff[1024];    // g*16 = float4-row offset
    __shared__ float  sred[1024];
    int tid = threadIdx.x;
    int pair0 = blockIdx.x * 1024;
    int pbase = pair0 >> 4;

    for (int i = tid; i < 1024; i += 256) gixs[i] = idx[pair0 + i];
    for (int i = tid; i < 4096; i += 256) xqn[i] = -g_xq[pbase*64 + i];

    float scP[3], shP[3];
    #pragma unroll
    for (int c = 0; c < 3; c++) {
        float mean = g_accP[c] / MF;
        float var  = g_accP[3+c] / MF - mean*mean;
        float sc   = gp[c] * rsqrtf(var + EPS);
        scP[c] = sc;
        shP[c] = bpbn[c] - mean*sc;
    }
    float w00 = Wp1[0], w01 = Wp1[1], w02 = Wp1[2];
    float w10 = Wp1[3], w11 = Wp1[4], w12 = Wp1[5];
    float w20 = Wp1[6], w21 = Wp1[7], w22 = Wp1[8];
    float c0 = bp1[0], c1 = bp1[1], c2 = bp1[2];
    __syncthreads();

    #pragma unroll
    for (int kk = 0; kk < 4; kk++) {
        int t = tid + kk*256;
        int n = pbase + (t >> 4);
        int g = gixs[t];
        goff[t] = g << 4;
        float r0 = p[g*3+0] - p[n*3+0];
        float r1 = p[g*3+1] - p[n*3+1];
        float r2 = p[g*3+2] - p[n*3+2];
        float v0 = c0 + r0*w00 + r1*w10 + r2*w20;
        float v1 = c1 + r0*w01 + r1*w11 + r2*w21;
        float v2 = c2 + r0*w02 + r1*w12 + r2*w22;
        float h0 = fmaxf(v0*scP[0] + shP[0], 0.f);
        float h1 = fmaxf(v1*scP[1] + shP[1], 0.f);
        float h2 = fmaxf(v2*scP[2] + shP[2], 0.f);
        float4 h = make_float4(h0, h1, h2, 0.f);
        prh4[t] = h;
        g_prh4[pair0 + t] = h;
    }
    __syncthreads();

    int cq = (tid & 15) * 4;
    int lof = tid & 15;
    float4 A0q = __ldg((const float4*)&Wp2[cq]);
    float4 A1q = __ldg((const float4*)&Wp2[64 + cq]);
    float4 A2q = __ldg((const float4*)&Wp2[128 + cq]);
    float4 Bq  = __ldg((const float4*)&bp2[cq]);
    ulonglong2 A0u = *(ulonglong2*)&A0q, A1u = *(ulonglong2*)&A1q;
    ulonglong2 A2u = *(ulonglong2*)&A2q, Bu  = *(ulonglong2*)&Bq;

    ull s_lo = 0, s_hi = 0, ss_lo = 0, ss_hi = 0;
    int pl = tid >> 4;
    #pragma unroll 4
    for (int k = 0; k < 64; k++) {
        int t = pl + 16*k;
        float4 xk4 = __ldg((const float4*)g_xk + goff[t] + lof);
        float4 h4 = prh4[t];
        ull h0p = pack2(h4.x, h4.x), h1p = pack2(h4.y, h4.y), h2p = pack2(h4.z, h4.z);
        ulonglong2 xku = *(ulonglong2*)&xk4;
        ulonglong2 xqu = *(ulonglong2*)&xqn[(t >> 4)*64 + cq];
        ull t_lo = ffma2(h2p, A2u.x, ffma2(h1p, A1u.x, ffma2(h0p, A0u.x, Bu.x)));
        ull t_hi = ffma2(h2p, A2u.y, ffma2(h1p, A1u.y, ffma2(h0p, A0u.y, Bu.y)));
        ull w_lo = fadd2(xku.x, fadd2(xqu.x, t_lo));
        ull w_hi = fadd2(xku.y, fadd2(xqu.y, t_hi));
        s_lo = fadd2(s_lo, w_lo); s_hi = fadd2(s_hi, w_hi);
        ss_lo = ffma2(w_lo, w_lo, ss_lo); ss_hi = ffma2(w_hi, w_hi, ss_hi);
    }

    float v[8];
    unpack2(s_lo, v[0], v[1]); unpack2(s_hi, v[2], v[3]);
    unpack2(ss_lo, v[4], v[5]); unpack2(ss_hi, v[6], v[7]);
    #pragma unroll
    for (int i = 0; i < 8; i++) v[i] += __shfl_xor_sync(0xffffffffu, v[i], 16);
    int lane = tid & 31, wrp = tid >> 5;
    if (lane < 16) {
        #pragma unroll
        for (int i = 0; i < 8; i++) sred[lane*64 + wrp*8 + i] = v[i];
    }
    __syncthreads();
    if (tid < 128) {
        int q = tid >> 3, vi = tid & 7;
        float s = 0.f;
        #pragma unroll
        for (int w = 0; w < 8; w++) s += sred[q*64 + w*8 + vi];
        int gi = (vi < 4) ? (q*4 + vi) : (64 + q*4 + vi - 4);
        atomicAdd(&g_accW[gi], s);
    }
}

// ---------------- K3: 16 lanes/pair, 2-way ILP + depth-1 prefetch, offset precompute ----------------
// grid 2048, block 256, 2 blocks/SM: 512 pairs (32 points) per block
__global__ void __launch_bounds__(256, 2) k3(
                   const int* __restrict__ idx,
                   const float* __restrict__ Wp2, const float* __restrict__ bp2,
                   const float* __restrict__ gw1, const float* __restrict__ bw1bn,
                   const float* __restrict__ Ww1, const float* __restrict__ bw1)
{
    __shared__ float xqn[32*64];     // -xq * sc
    __shared__ int   gixs[512];      // g*16 (ulonglong2-row offset)
    __shared__ float sS[64];
    __shared__ float wred[8*16];
    int tid = threadIdx.x;
    int lane = tid & 31, wrp = tid >> 5;
    int pair0 = blockIdx.x * 512;
    int pbase = pair0 >> 4;
    int cq = (tid & 15) * 4;
    int lof = tid & 15;              // ulonglong2 offset within row (cq/4)
    int slot = tid >> 4;
    int P = (lane >> 2) & 3;

    if (tid < 64) {
        int c = tid;
        float mean = g_accW[c] / MF;
        float var  = g_accW[64 + c] / MF - mean*mean;
        sS[c] = gw1[c] * rsqrtf(var + EPS);
    }
    for (int i = tid; i < 512; i += 256) gixs[i] = idx[pair0 + i] << 4;

    ull A0u[2], A1u[2], A2u[2], Bu[2], Su[2];
    {
        float a0[4], a1[4], a2[4], bb[4], sv[4];
        #pragma unroll
        for (int e = 0; e < 4; e++) {
            int c = cq + e;
            float mean = g_accW[c] / MF;
            float var  = g_accW[64 + c] / MF - mean*mean;
            float sc   = gw1[c] * rsqrtf(var + EPS);
            float sh   = bw1bn[c] - mean*sc;
            sv[e] = sc;
            a0[e] = Wp2[c]*sc; a1[e] = Wp2[64+c]*sc; a2[e] = Wp2[128+c]*sc;
            bb[e] = bp2[c]*sc + sh;
        }
        A0u[0] = pack2(a0[0], a0[1]); A0u[1] = pack2(a0[2], a0[3]);
        A1u[0] = pack2(a1[0], a1[1]); A1u[1] = pack2(a1[2], a1[3]);
        A2u[0] = pack2(a2[0], a2[1]); A2u[1] = pack2(a2[2], a2[3]);
        Bu[0]  = pack2(bb[0], bb[1]); Bu[1]  = pack2(bb[2], bb[3]);
        Su[0]  = pack2(sv[0], sv[1]); Su[1]  = pack2(sv[2], sv[3]);
    }

    ull Wr[4][4];
    #pragma unroll
    for (int e = 0; e < 4; e++)
        #pragma unroll
        for (int s = 0; s < 4; s++)
            Wr[e][s] = __ldg((const ull*)Ww1 + (cq + e)*4 + (P ^ s));
    ull biasu = __ldg((const ull*)bw1 + P);
    __syncthreads();

    for (int i = tid; i < 2048; i += 256)
        xqn[i] = -g_xq[(size_t)pbase*64 + i] * sS[i & 63];
    __syncthreads();

    const ulonglong2* xkb = (const ulonglong2*)g_xk;
    ull stS = 0, stQ = 0;

    // ---- prologue: load group k=0 (pairs slot, slot+16) ----
    float4 hA = __ldg(&g_prh4[pair0 + slot]);
    float4 hB = __ldg(&g_prh4[pair0 + slot + 16]);
    ulonglong2 xkA = __ldg(xkb + gixs[slot] + lof);
    ulonglong2 xkB = __ldg(xkb + gixs[slot + 16] + lof);

    #pragma unroll 1
    for (int k = 0; k < 32; k += 2) {
        int li0 = slot + (k << 4);
        int li1 = li0 + 16;
        int pr_0 = pair0 + li0, pr_1 = pair0 + li1;

        // prefetch next group's gathers
        float4 hA_n, hB_n; ulonglong2 xkA_n, xkB_n;
        bool more = (k < 30);
        if (more) {
            int li0n = li0 + 32, li1n = li0 + 48;
            hA_n = __ldg(&g_prh4[pair0 + li0n]);
            hB_n = __ldg(&g_prh4[pair0 + li1n]);
            xkA_n = __ldg(xkb + gixs[li0n] + lof);
            xkB_n = __ldg(xkb + gixs[li1n] + lof);
        }

        ulonglong2 xqA = *(const ulonglong2*)&xqn[(k << 6) + cq];
        ulonglong2 xqB = *(const ulonglong2*)&xqn[((k + 1) << 6) + cq];

        // ---- chain A ----
        ull a0A, a1A, a2A, a3A;
        {
            ull h0p = pack2(hA.x, hA.x), h1p = pack2(hA.y, hA.y), h2p = pack2(hA.z, hA.z);
            ull r_lo = ffma2(h2p, A2u[0], ffma2(h1p, A1u[0], ffma2(h0p, A0u[0], Bu[0])));
            ull r_hi = ffma2(h2p, A2u[1], ffma2(h1p, A1u[1], ffma2(h0p, A0u[1], Bu[1])));
            ull w_lo = ffma2(xkA.x, Su[0], fadd2(xqA.x, r_lo));
            ull w_hi = ffma2(xkA.y, Su[1], fadd2(xqA.y, r_hi));
            float w0, w1, w2, w3;
            unpack2(w_lo, w0, w1); unpack2(w_hi, w2, w3);
            ull wp0 = pack2(fmaxf(w0,0.f), fmaxf(w0,0.f));
            ull wp1 = pack2(fmaxf(w1,0.f), fmaxf(w1,0.f));
            ull wp2_ = pack2(fmaxf(w2,0.f), fmaxf(w2,0.f));
            ull wp3 = pack2(fmaxf(w3,0.f), fmaxf(w3,0.f));
            a0A = fmul2(wp0, Wr[0][0]); a1A = fmul2(wp0, Wr[0][1]);
            a2A = fmul2(wp0, Wr[0][2]); a3A = fmul2(wp0, Wr[0][3]);
            a0A = ffma2(wp1, Wr[1][0], a0A); a1A = ffma2(wp1, Wr[1][1], a1A);
            a2A = ffma2(wp1, Wr[1][2], a2A); a3A = ffma2(wp1, Wr[1][3], a3A);
            a0A = ffma2(wp2_, Wr[2][0], a0A); a1A = ffma2(wp2_, Wr[2][1], a1A);
            a2A = ffma2(wp2_, Wr[2][2], a2A); a3A = ffma2(wp2_, Wr[2][3], a3A);
            a0A = ffma2(wp3, Wr[3][0], a0A); a1A = ffma2(wp3, Wr[3][1], a1A);
            a2A = ffma2(wp3, Wr[3][2], a2A); a3A = ffma2(wp3, Wr[3][3], a3A);
        }
        // ---- chain B ----
        ull a0B, a1B, a2B, a3B;
        {
            ull h0p = pack2(hB.x, hB.x), h1p = pack2(hB.y, hB.y), h2p = pack2(hB.z, hB.z);
            ull r_lo = ffma2(h2p, A2u[0], ffma2(h1p, A1u[0], ffma2(h0p, A0u[0], Bu[0])));
            ull r_hi = ffma2(h2p, A2u[1], ffma2(h1p, A1u[1], ffma2(h0p, A0u[1], Bu[1])));
            ull w_lo = ffma2(xkB.x, Su[0], fadd2(xqB.x, r_lo));
            ull w_hi = ffma2(xkB.y, Su[1], fadd2(xqB.y, r_hi));
            float w0, w1, w2, w3;
            unpack2(w_lo, w0, w1); unpack2(w_hi, w2, w3);
            ull wp0 = pack2(fmaxf(w0,0.f), fmaxf(w0,0.f));
            ull wp1 = pack2(fmaxf(w1,0.f), fmaxf(w1,0.f));
            ull wp2_ = pack2(fmaxf(w2,0.f), fmaxf(w2,0.f));
            ull wp3 = pack2(fmaxf(w3,0.f), fmaxf(w3,0.f));
            a0B = fmul2(wp0, Wr[0][0]); a1B = fmul2(wp0, Wr[0][1]);
            a2B = fmul2(wp0, Wr[0][2]); a3B = fmul2(wp0, Wr[0][3]);
            a0B = ffma2(wp1, Wr[1][0], a0B); a1B = ffma2(wp1, Wr[1][1], a1B);
            a2B = ffma2(wp1, Wr[1][2], a2B); a3B = ffma2(wp1, Wr[1][3], a3B);
            a0B = ffma2(wp2_, Wr[2][0], a0B); a1B = ffma2(wp2_, Wr[2][1], a1B);
            a2B = ffma2(wp2_, Wr[2][2], a2B); a3B = ffma2(wp2_, Wr[2][3], a3B);
            a0B = ffma2(wp3, Wr[3][0], a0B); a1B = ffma2(wp3, Wr[3][1], a1B);
            a2B = ffma2(wp3, Wr[3][2], a2B); a3B = ffma2(wp3, Wr[3][3], a3B);
        }

        // ---- interleaved butterflies ----
        ull tA2 = __shfl_xor_sync(0xffffffffu, a2A, 8);
        ull tB2 = __shfl_xor_sync(0xffffffffu, a2B, 8);
        ull tA3 = __shfl_xor_sync(0xffffffffu, a3A, 8);
        ull tB3 = __shfl_xor_sync(0xffffffffu, a3B, 8);
        a0A = fadd2(a0A, tA2); a0B = fadd2(a0B, tB2);
        a1A = fadd2(a1A, tA3); a1B = fadd2(a1B, tB3);
        ull uA = __shfl_xor_sync(0xffffffffu, a1A, 4);
        ull uB = __shfl_xor_sync(0xffffffffu, a1B, 4);
        a0A = fadd2(a0A, uA); a0B = fadd2(a0B, uB);
        uA = __shfl_xor_sync(0xffffffffu, a0A, 2);
        uB = __shfl_xor_sync(0xffffffffu, a0B, 2);
        a0A = fadd2(a0A, uA); a0B = fadd2(a0B, uB);
        uA = __shfl_xor_sync(0xffffffffu, a0A, 1);
        uB = __shfl_xor_sync(0xffffffffu, a0B, 1);
        a0A = fadd2(fadd2(a0A, uA), biasu);
        a0B = fadd2(fadd2(a0B, uB), biasu);

        if ((lane & 3) == 0) {
            *((ull*)g_w1 + (size_t)pr_0*4 + P) = a0A;
            *((ull*)g_w1 + (size_t)pr_1*4 + P) = a0B;
        }

        stS = fadd2(stS, fadd2(a0A, a0B));
        stQ = ffma2(a0A, a0A, stQ);
        stQ = ffma2(a0B, a0B, stQ);

        if (more) {
            hA = hA_n; hB = hB_n; xkA = xkA_n; xkB = xkB_n;
        }
    }

    stS = fadd2(stS, __shfl_xor_sync(0xffffffffu, stS, 16));
    stQ = fadd2(stQ, __shfl_xor_sync(0xffffffffu, stQ, 16));
    if (lane < 16 && (lane & 3) == 0) {
        float s0, s1, q0, q1;
        unpack2(stS, s0, s1); unpack2(stQ, q0, q1);
        wred[wrp*16 + 2*P]     = s0;
        wred[wrp*16 + 2*P + 1] = s1;
        wred[wrp*16 + 8 + 2*P]     = q0;
        wred[wrp*16 + 8 + 2*P + 1] = q1;
    }
    __syncthreads();
    if (tid < 16) {
        float s = 0.f;
        #pragma unroll
        for (int w = 0; w < 8; w++) s += wred[w*16 + tid];
        atomicAdd(&g_accU[tid], s);
    }
}

// ---------------- K4: bn2+relu -> @Ww2 -> softmax(ns) -> aggregate ----------------
__global__ void __launch_bounds__(256) k4(
                   const int* __restrict__ idx,
                   const float* __restrict__ Wp2, const float* __restrict__ bp2,
                   const float* __restrict__ gw2, const float* __restrict__ bw2bn,
                   const float* __restrict__ Ww2, const float* __restrict__ bw2,
                   float* __restrict__ out)
{
    __shared__ float w1s[4][128];
    __shared__ float hs[4][128];
    __shared__ float w2s[4][128];
    __shared__ float prs[4][48];
    __shared__ int   gix4[4][16];    // g*64
    __shared__ float wp2s[192], bp2s[64], wws[64], bws[8];
    int tid = threadIdx.x;
    int sub = tid >> 6, ct = tid & 63;
    int n = blockIdx.x*4 + sub;

    for (int i = tid; i < 192; i += 256) wp2s[i] = Wp2[i];
    if (tid < 64) { bp2s[tid] = bp2[tid]; wws[tid] = Ww2[tid]; }
    if (tid < 8)  bws[tid] = bw2[tid];

    w1s[sub][ct]      = g_w1[n*128 + ct];
    w1s[sub][ct + 64] = g_w1[n*128 + ct + 64];
    if (ct < 16) {
        gix4[sub][ct] = idx[n*16 + ct] << 6;
        float4 h = g_prh4[n*16 + ct];
        prs[sub][ct] = h.x; prs[sub][16 + ct] = h.y; prs[sub][32 + ct] = h.z;
    }

    int u = ct & 7;
    float mean = g_accU[u] / MF;
    float var  = g_accU[8 + u] / MF - mean*mean;
    float sc2  = gw2[u] * rsqrtf(var + EPS);
    float sh2  = bw2bn[u] - mean*sc2;
    __syncthreads();

    hs[sub][ct]      = fmaxf(w1s[sub][ct]*sc2 + sh2, 0.f);
    hs[sub][ct + 64] = fmaxf(w1s[sub][ct + 64]*sc2 + sh2, 0.f);
    __syncthreads();

    #pragma unroll
    for (int o = ct; o < 128; o += 64) {
        int j = o >> 3, t = o & 7;
        float v = bws[t];
        #pragma unroll
        for (int uu = 0; uu < 8; uu++) v += hs[sub][j*8 + uu] * wws[uu*8 + t];
        w2s[sub][o] = v;
    }
    __syncthreads();

    if (ct < 8) {
        int t = ct;
        float m = -1e30f;
        #pragma unroll
        for (int j = 0; j < 16; j++) m = fmaxf(m, w2s[sub][j*8 + t]);
        float e[16], ssum = 0.f;
        #pragma unroll
        for (int j = 0; j < 16; j++) { e[j] = __expf(w2s[sub][j*8 + t] - m); ssum += e[j]; }
        float inv = 1.f / ssum;
        #pragma unroll
        for (int j = 0; j < 16; j++) w2s[sub][j*8 + t] = e[j] * inv;
    }
    __syncthreads();

    int t = ct & 7;
    float a0 = wp2s[ct], a1 = wp2s[64 + ct], a2 = wp2s[128 + ct], bb = bp2s[ct];
    float acc = 0.f;
    #pragma unroll
    for (int j = 0; j < 16; j++) {
        int goff = gix4[sub][j];
        float v = __ldg(&g_xv[goff + ct]);
        float pr = fmaf(prs[sub][32 + j], a2, fmaf(prs[sub][16 + j], a1, fmaf(prs[sub][j], a0, bb)));
        acc += (v + pr) * w2s[sub][j*8 + t];
    }
    out[n*64 + ct] = acc;
}

// ---------------- launch ----------------
extern "C" void kernel_launch(void* const* d_in, const int* in_sizes, int n_in,
                              void* d_out, int out_size)
{
    const float* p    = (const float*)d_in[0];
    const float* x    = (const float*)d_in[1];
    const int*   idx  = (const int*)d_in[2];
    const float* Wq   = (const float*)d_in[3];
    const float* bq   = (const float*)d_in[4];
    const float* Wk   = (const float*)d_in[5];
    const float* bk   = (const float*)d_in[6];
    const float* Wv   = (const float*)d_in[7];
    const float* bv   = (const float*)d_in[8];
    const float* Wp1  = (const float*)d_in[9];
    const float* bp1  = (const float*)d_in[10];
    const float* gp   = (const float*)d_in[11];
    const float* bpbn = (const float*)d_in[12];
    const float* Wp2  = (const float*)d_in[13];
    const float* bp2  = (const float*)d_in[14];
    const float* gw1  = (const float*)d_in[15];
    const float* bw1bn= (const float*)d_in[16];
    const float* Ww1  = (const float*)d_in[17];
    const float* bw1  = (const float*)d_in[18];
    const float* gw2  = (const float*)d_in[19];
    const float* bw2bn= (const float*)d_in[20];
    const float* Ww2  = (const float*)d_in[21];
    const float* bw2  = (const float*)d_in[22];
    float* out = (float*)d_out;

    size_t smem1 = (size_t)(64*48*4 + 64*68 + 48*4) * 4;  // ~66KB
    cudaFuncSetAttribute(k1, cudaFuncAttributeMaxDynamicSharedMemorySize, (int)smem1);

    k_zero<<<1, 256>>>();
    k1<<<1024, 256, smem1>>>(x, p, idx, Wq, bq, Wk, bk, Wv, bv, Wp1, bp1);
    k2<<<1024, 256>>>(p, idx, Wp1, bp1, gp, bpbn, Wp2, bp2);
    k3<<<2048, 256>>>(idx, Wp2, bp2, gw1, bw1bn, Ww1, bw1);
    k4<<<16384, 256>>>(idx, Wp2, bp2, gw2, bw2bn, Ww2, bw2, out);
}

// round 9
// speedup vs baseline: 1.0300x; 1.0075x over previous
#include <cuda_runtime.h>

#define NPTS 65536
#define NS 16
#define NPAIR (NPTS*NS)
#define MF 1048576.0f
#define EPS 1e-5f

typedef unsigned long long ull;

__device__ __forceinline__ ull ffma2(ull a, ull b, ull c) {
    ull d; asm("fma.rn.f32x2 %0,%1,%2,%3;" : "=l"(d) : "l"(a), "l"(b), "l"(c)); return d;
}
__device__ __forceinline__ ull fmul2(ull a, ull b) {
    ull d; asm("mul.rn.f32x2 %0,%1,%2;" : "=l"(d) : "l"(a), "l"(b)); return d;
}
__device__ __forceinline__ ull fadd2(ull a, ull b) {
    ull d; asm("add.rn.f32x2 %0,%1,%2;" : "=l"(d) : "l"(a), "l"(b)); return d;
}
__device__ __forceinline__ ull pack2(float lo, float hi) {
    ull d; asm("mov.b64 %0,{%1,%2};" : "=l"(d) : "f"(lo), "f"(hi)); return d;
}
__device__ __forceinline__ void unpack2(ull v, float& lo, float& hi) {
    asm("mov.b64 {%0,%1},%2;" : "=f"(lo), "=f"(hi) : "l"(v));
}

// ---------------- scratch ----------------
__device__ float  g_xq[NPTS*64];
__device__ float  g_xk[NPTS*64];
__device__ float  g_xv[NPTS*64];
__device__ float4 g_prh4[NPAIR];   // {h0,h1,h2,0} per pair
__device__ float  g_w1[NPAIR*8];
__device__ float  g_accP[6];
__device__ float  g_accW[128];
__device__ float  g_accU[16];

__global__ void k_zero() {
    int t = threadIdx.x;
    if (t < 6)   g_accP[t] = 0.f;
    if (t < 128) g_accW[t] = 0.f;
    if (t < 16)  g_accU[t] = 0.f;
}

// ---------------- K1: qkv GEMM (64 pts/block) + pr1 BN stats ----------------
__global__ void __launch_bounds__(256) k1(
                   const float* __restrict__ x, const float* __restrict__ p,
                   const int* __restrict__ idx,
                   const float* __restrict__ Wq, const float* __restrict__ bq,
                   const float* __restrict__ Wk, const float* __restrict__ bk,
                   const float* __restrict__ Wv, const float* __restrict__ bv,
                   const float* __restrict__ Wp1, const float* __restrict__ bp1)
{
    extern __shared__ float sm[];
    float4* ws4  = (float4*)sm;            // [64][48] float4
    float*  xs   = sm + 64*48*4;           // [64][68]
    float4* bsm4 = (float4*)(xs + 64*68);  // [48]
    int tid = threadIdx.x;
    int base = blockIdx.x * 64;

    for (int i = tid; i < 64*48; i += 256) {
        int k = i / 48, r = i - k*48;
        int seg = r >> 4, tx = r & 15;
        const float4* src = (seg == 0) ? (const float4*)Wq :
                            (seg == 1) ? (const float4*)Wk : (const float4*)Wv;
        ws4[i] = src[k*16 + tx];
    }
    {
        float4* xs4 = (float4*)xs;
        for (int i = tid; i < 64*16; i += 256) {
            int pt = i >> 4, kk = i & 15;
            xs4[pt*17 + kk] = ((const float4*)x)[(base + pt)*16 + kk];
        }
    }
    if (tid < 48) {
        int seg = tid >> 4, tx = tid & 15;
        const float4* src = (seg == 0) ? (const float4*)bq :
                            (seg == 1) ? (const float4*)bk : (const float4*)bv;
        bsm4[tid] = src[tx];
    }
    __syncthreads();

    int tx = tid & 15, ty = tid >> 4;
    ulonglong2 acc[3][4];
    #pragma unroll
    for (int s = 0; s < 3; s++) {
        ulonglong2 b = ((ulonglong2*)bsm4)[s*16 + tx];
        #pragma unroll
        for (int r = 0; r < 4; r++) acc[s][r] = b;
    }

    #pragma unroll 4
    for (int kq = 0; kq < 16; kq++) {
        float4 aq[4];
        #pragma unroll
        for (int r = 0; r < 4; r++) aq[r] = *(float4*)&xs[(ty*4 + r)*68 + kq*4];
        #pragma unroll
        for (int e = 0; e < 4; e++) {
            int k = kq*4 + e;
            ull ap[4];
            #pragma unroll
            for (int r = 0; r < 4; r++) {
                float av = ((float*)&aq[r])[e];
                ap[r] = pack2(av, av);
            }
            #pragma unroll
            for (int s = 0; s < 3; s++) {
                ulonglong2 w2 = *(ulonglong2*)&ws4[k*48 + s*16 + tx];
                #pragma unroll
                for (int r = 0; r < 4; r++) {
                    acc[s][r].x = ffma2(ap[r], w2.x, acc[s][r].x);
                    acc[s][r].y = ffma2(ap[r], w2.y, acc[s][r].y);
                }
            }
        }
    }

    #pragma unroll
    for (int r = 0; r < 4; r++) {
        int pt = base + ty*4 + r;
        ((ulonglong2*)&g_xq[pt*64])[tx] = acc[0][r];
        ((ulonglong2*)&g_xk[pt*64])[tx] = acc[1][r];
        ((ulonglong2*)&g_xv[pt*64])[tx] = acc[2][r];
    }

    // ---- pr1 stats over this block's 1024 pairs ----
    float w00 = Wp1[0], w01 = Wp1[1], w02 = Wp1[2];
    float w10 = Wp1[3], w11 = Wp1[4], w12 = Wp1[5];
    float w20 = Wp1[6], w21 = Wp1[7], w22 = Wp1[8];
    float c0 = bp1[0], c1 = bp1[1], c2 = bp1[2];
    float s0=0,s1=0,s2=0,q0=0,q1=0,q2=0;
    for (int t = tid; t < 1024; t += 256) {
        int n = base + (t >> 4);
        int g = idx[n*NS + (t & 15)];
        float r0 = p[g*3+0] - p[n*3+0];
        float r1 = p[g*3+1] - p[n*3+1];
        float r2 = p[g*3+2] - p[n*3+2];
        float v0 = c0 + r0*w00 + r1*w10 + r2*w20;
        float v1 = c1 + r0*w01 + r1*w11 + r2*w21;
        float v2 = c2 + r0*w02 + r1*w12 + r2*w22;
        s0 += v0; s1 += v1; s2 += v2;
        q0 += v0*v0; q1 += v1*v1; q2 += v2*v2;
    }
    #pragma unroll
    for (int off = 16; off; off >>= 1) {
        s0 += __shfl_xor_sync(0xffffffffu, s0, off);
        s1 += __shfl_xor_sync(0xffffffffu, s1, off);
        s2 += __shfl_xor_sync(0xffffffffu, s2, off);
        q0 += __shfl_xor_sync(0xffffffffu, q0, off);
        q1 += __shfl_xor_sync(0xffffffffu, q1, off);
        q2 += __shfl_xor_sync(0xffffffffu, q2, off);
    }
    __syncthreads();
    float* red = sm;
    int lane = tid & 31, wrp = tid >> 5;
    if (lane == 0) {
        red[wrp*6+0] = s0; red[wrp*6+1] = s1; red[wrp*6+2] = s2;
        red[wrp*6+3] = q0; red[wrp*6+4] = q1; red[wrp*6+5] = q2;
    }
    __syncthreads();
    if (tid < 6) {
        float t2 = 0.f;
        #pragma unroll
        for (int w = 0; w < 8; w++) t2 += red[w*6 + tid];
        atomicAdd(&g_accP[tid], t2);
    }
}

// ---------------- K2: pr_hat + w-channel BN stats (2-way interleaved phase-B) ----------------
__global__ void __launch_bounds__(256) k2(
                   const float* __restrict__ p, const int* __restrict__ idx,
                   const float* __restrict__ Wp1, const float* __restrict__ bp1,
                   const float* __restrict__ gp, const float* __restrict__ bpbn,
                   const float* __restrict__ Wp2, const float* __restrict__ bp2)
{
    __shared__ float4 prh4[1024];
    __shared__ float  xqn[64*64];
    __shared__ int    gixs[1024];
    __shared__ int    goff[1024];    // g*16 = float4-row offset
    __shared__ float  sred[1024];
    int tid = threadIdx.x;
    int pair0 = blockIdx.x * 1024;
    int pbase = pair0 >> 4;

    for (int i = tid; i < 1024; i += 256) gixs[i] = idx[pair0 + i];
    for (int i = tid; i < 4096; i += 256) xqn[i] = -g_xq[pbase*64 + i];

    float scP[3], shP[3];
    #pragma unroll
    for (int c = 0; c < 3; c++) {
        float mean = g_accP[c] / MF;
        float var  = g_accP[3+c] / MF - mean*mean;
        float sc   = gp[c] * rsqrtf(var + EPS);
        scP[c] = sc;
        shP[c] = bpbn[c] - mean*sc;
    }
    float w00 = Wp1[0], w01 = Wp1[1], w02 = Wp1[2];
    float w10 = Wp1[3], w11 = Wp1[4], w12 = Wp1[5];
    float w20 = Wp1[6], w21 = Wp1[7], w22 = Wp1[8];
    float c0 = bp1[0], c1 = bp1[1], c2 = bp1[2];
    __syncthreads();

    #pragma unroll
    for (int kk = 0; kk < 4; kk++) {
        int t = tid + kk*256;
        int n = pbase + (t >> 4);
        int g = gixs[t];
        goff[t] = g << 4;
        float r0 = p[g*3+0] - p[n*3+0];
        float r1 = p[g*3+1] - p[n*3+1];
        float r2 = p[g*3+2] - p[n*3+2];
        float v0 = c0 + r0*w00 + r1*w10 + r2*w20;
        float v1 = c1 + r0*w01 + r1*w11 + r2*w21;
        float v2 = c2 + r0*w02 + r1*w12 + r2*w22;
        float h0 = fmaxf(v0*scP[0] + shP[0], 0.f);
        float h1 = fmaxf(v1*scP[1] + shP[1], 0.f);
        float h2 = fmaxf(v2*scP[2] + shP[2], 0.f);
        float4 h = make_float4(h0, h1, h2, 0.f);
        prh4[t] = h;
        g_prh4[pair0 + t] = h;
    }
    __syncthreads();

    int cq = (tid & 15) * 4;
    int lof = tid & 15;
    float4 A0q = __ldg((const float4*)&Wp2[cq]);
    float4 A1q = __ldg((const float4*)&Wp2[64 + cq]);
    float4 A2q = __ldg((const float4*)&Wp2[128 + cq]);
    float4 Bq  = __ldg((const float4*)&bp2[cq]);
    ulonglong2 A0u = *(ulonglong2*)&A0q, A1u = *(ulonglong2*)&A1q;
    ulonglong2 A2u = *(ulonglong2*)&A2q, Bu  = *(ulonglong2*)&Bq;

    ull s_lo = 0, s_hi = 0, ss_lo = 0, ss_hi = 0;
    int pl = tid >> 4;
    #pragma unroll 1
    for (int k = 0; k < 64; k += 2) {
        int t0 = pl + 16*k;
        int t1 = t0 + 16;
        float4 xkq0 = __ldg((const float4*)g_xk + goff[t0] + lof);
        float4 xkq1 = __ldg((const float4*)g_xk + goff[t1] + lof);
        float4 h40 = prh4[t0];
        float4 h41 = prh4[t1];
        ulonglong2 xqu0 = *(ulonglong2*)&xqn[(t0 >> 4)*64 + cq];
        ulonglong2 xqu1 = *(ulonglong2*)&xqn[(t1 >> 4)*64 + cq];
        {
            ull h0p = pack2(h40.x, h40.x), h1p = pack2(h40.y, h40.y), h2p = pack2(h40.z, h40.z);
            ulonglong2 xku = *(ulonglong2*)&xkq0;
            ull t_lo = ffma2(h2p, A2u.x, ffma2(h1p, A1u.x, ffma2(h0p, A0u.x, Bu.x)));
            ull t_hi = ffma2(h2p, A2u.y, ffma2(h1p, A1u.y, ffma2(h0p, A0u.y, Bu.y)));
            ull w_lo = fadd2(xku.x, fadd2(xqu0.x, t_lo));
            ull w_hi = fadd2(xku.y, fadd2(xqu0.y, t_hi));
            s_lo = fadd2(s_lo, w_lo); s_hi = fadd2(s_hi, w_hi);
            ss_lo = ffma2(w_lo, w_lo, ss_lo); ss_hi = ffma2(w_hi, w_hi, ss_hi);
        }
        {
            ull h0p = pack2(h41.x, h41.x), h1p = pack2(h41.y, h41.y), h2p = pack2(h41.z, h41.z);
            ulonglong2 xku = *(ulonglong2*)&xkq1;
            ull t_lo = ffma2(h2p, A2u.x, ffma2(h1p, A1u.x, ffma2(h0p, A0u.x, Bu.x)));
            ull t_hi = ffma2(h2p, A2u.y, ffma2(h1p, A1u.y, ffma2(h0p, A0u.y, Bu.y)));
            ull w_lo = fadd2(xku.x, fadd2(xqu1.x, t_lo));
            ull w_hi = fadd2(xku.y, fadd2(xqu1.y, t_hi));
            s_lo = fadd2(s_lo, w_lo); s_hi = fadd2(s_hi, w_hi);
            ss_lo = ffma2(w_lo, w_lo, ss_lo); ss_hi = ffma2(w_hi, w_hi, ss_hi);
        }
    }

    float v[8];
    unpack2(s_lo, v[0], v[1]); unpack2(s_hi, v[2], v[3]);
    unpack2(ss_lo, v[4], v[5]); unpack2(ss_hi, v[6], v[7]);
    #pragma unroll
    for (int i = 0; i < 8; i++) v[i] += __shfl_xor_sync(0xffffffffu, v[i], 16);
    int lane = tid & 31, wrp = tid >> 5;
    if (lane < 16) {
        #pragma unroll
        for (int i = 0; i < 8; i++) sred[lane*64 + wrp*8 + i] = v[i];
    }
    __syncthreads();
    if (tid < 128) {
        int q = tid >> 3, vi = tid & 7;
        float s = 0.f;
        #pragma unroll
        for (int w = 0; w < 8; w++) s += sred[q*64 + w*8 + vi];
        int gi = (vi < 4) ? (q*4 + vi) : (64 + q*4 + vi - 4);
        atomicAdd(&g_accW[gi], s);
    }
}

// ---------------- K3: 16 lanes/pair, reg tables, 2-way interleaved (R6) + goff ----------------
// grid 2048, block 256, 2 blocks/SM: 512 pairs (32 points) per block
__global__ void __launch_bounds__(256, 2) k3(
                   const int* __restrict__ idx,
                   const float* __restrict__ Wp2, const float* __restrict__ bp2,
                   const float* __restrict__ gw1, const float* __restrict__ bw1bn,
                   const float* __restrict__ Ww1, const float* __restrict__ bw1)
{
    __shared__ float xqn[32*64];     // -xq * sc
    __shared__ int   gixs[512];      // g*16 (ulonglong2-row offset)
    __shared__ float sS[64];
    __shared__ float wred[8*16];
    int tid = threadIdx.x;
    int lane = tid & 31, wrp = tid >> 5;
    int pair0 = blockIdx.x * 512;
    int pbase = pair0 >> 4;
    int cq = (tid & 15) * 4;
    int lof = tid & 15;
    int slot = tid >> 4;
    int P = (lane >> 2) & 3;

    if (tid < 64) {
        int c = tid;
        float mean = g_accW[c] / MF;
        float var  = g_accW[64 + c] / MF - mean*mean;
        sS[c] = gw1[c] * rsqrtf(var + EPS);
    }
    for (int i = tid; i < 512; i += 256) gixs[i] = idx[pair0 + i] << 4;

    ull A0u[2], A1u[2], A2u[2], Bu[2], Su[2];
    {
        float a0[4], a1[4], a2[4], bb[4], sv[4];
        #pragma unroll
        for (int e = 0; e < 4; e++) {
            int c = cq + e;
            float mean = g_accW[c] / MF;
            float var  = g_accW[64 + c] / MF - mean*mean;
            float sc   = gw1[c] * rsqrtf(var + EPS);
            float sh   = bw1bn[c] - mean*sc;
            sv[e] = sc;
            a0[e] = Wp2[c]*sc; a1[e] = Wp2[64+c]*sc; a2[e] = Wp2[128+c]*sc;
            bb[e] = bp2[c]*sc + sh;
        }
        A0u[0] = pack2(a0[0], a0[1]); A0u[1] = pack2(a0[2], a0[3]);
        A1u[0] = pack2(a1[0], a1[1]); A1u[1] = pack2(a1[2], a1[3]);
        A2u[0] = pack2(a2[0], a2[1]); A2u[1] = pack2(a2[2], a2[3]);
        Bu[0]  = pack2(bb[0], bb[1]); Bu[1]  = pack2(bb[2], bb[3]);
        Su[0]  = pack2(sv[0], sv[1]); Su[1]  = pack2(sv[2], sv[3]);
    }

    ull Wr[4][4];
    #pragma unroll
    for (int e = 0; e < 4; e++)
        #pragma unroll
        for (int s = 0; s < 4; s++)
            Wr[e][s] = __ldg((const ull*)Ww1 + (cq + e)*4 + (P ^ s));
    ull biasu = __ldg((const ull*)bw1 + P);
    __syncthreads();

    for (int i = tid; i < 2048; i += 256)
        xqn[i] = -g_xq[(size_t)pbase*64 + i] * sS[i & 63];
    __syncthreads();

    const ulonglong2* xkb = (const ulonglong2*)g_xk;
    ull stS = 0, stQ = 0;

    #pragma unroll 1
    for (int k = 0; k < 32; k += 2) {
        // ---- batched loads for both pairs ----
        int li0 = slot + (k << 4);
        int li1 = li0 + 16;
        int pr_0 = pair0 + li0, pr_1 = pair0 + li1;
        float4 hA = __ldg(&g_prh4[pr_0]);
        float4 hB = __ldg(&g_prh4[pr_1]);
        ulonglong2 xkA = __ldg(xkb + gixs[li0] + lof);
        ulonglong2 xkB = __ldg(xkb + gixs[li1] + lof);
        ulonglong2 xqA = *(const ulonglong2*)&xqn[(k << 6) + cq];
        ulonglong2 xqB = *(const ulonglong2*)&xqn[((k + 1) << 6) + cq];

        // ---- chain A ----
        ull a0A, a1A, a2A, a3A;
        {
            ull h0p = pack2(hA.x, hA.x), h1p = pack2(hA.y, hA.y), h2p = pack2(hA.z, hA.z);
            ull r_lo = ffma2(h2p, A2u[0], ffma2(h1p, A1u[0], ffma2(h0p, A0u[0], Bu[0])));
            ull r_hi = ffma2(h2p, A2u[1], ffma2(h1p, A1u[1], ffma2(h0p, A0u[1], Bu[1])));
            ull w_lo = ffma2(xkA.x, Su[0], fadd2(xqA.x, r_lo));
            ull w_hi = ffma2(xkA.y, Su[1], fadd2(xqA.y, r_hi));
            float w0, w1, w2, w3;
            unpack2(w_lo, w0, w1); unpack2(w_hi, w2, w3);
            ull wp0 = pack2(fmaxf(w0,0.f), fmaxf(w0,0.f));
            ull wp1 = pack2(fmaxf(w1,0.f), fmaxf(w1,0.f));
            ull wp2_ = pack2(fmaxf(w2,0.f), fmaxf(w2,0.f));
            ull wp3 = pack2(fmaxf(w3,0.f), fmaxf(w3,0.f));
            a0A = fmul2(wp0, Wr[0][0]); a1A = fmul2(wp0, Wr[0][1]);
            a2A = fmul2(wp0, Wr[0][2]); a3A = fmul2(wp0, Wr[0][3]);
            a0A = ffma2(wp1, Wr[1][0], a0A); a1A = ffma2(wp1, Wr[1][1], a1A);
            a2A = ffma2(wp1, Wr[1][2], a2A); a3A = ffma2(wp1, Wr[1][3], a3A);
            a0A = ffma2(wp2_, Wr[2][0], a0A); a1A = ffma2(wp2_, Wr[2][1], a1A);
            a2A = ffma2(wp2_, Wr[2][2], a2A); a3A = ffma2(wp2_, Wr[2][3], a3A);
            a0A = ffma2(wp3, Wr[3][0], a0A); a1A = ffma2(wp3, Wr[3][1], a1A);
            a2A = ffma2(wp3, Wr[3][2], a2A); a3A = ffma2(wp3, Wr[3][3], a3A);
        }
        // ---- chain B ----
        ull a0B, a1B, a2B, a3B;
        {
            ull h0p = pack2(hB.x, hB.x), h1p = pack2(hB.y, hB.y), h2p = pack2(hB.z, hB.z);
            ull r_lo = ffma2(h2p, A2u[0], ffma2(h1p, A1u[0], ffma2(h0p, A0u[0], Bu[0])));
            ull r_hi = ffma2(h2p, A2u[1], ffma2(h1p, A1u[1], ffma2(h0p, A0u[1], Bu[1])));
            ull w_lo = ffma2(xkB.x, Su[0], fadd2(xqB.x, r_lo));
            ull w_hi = ffma2(xkB.y, Su[1], fadd2(xqB.y, r_hi));
            float w0, w1, w2, w3;
            unpack2(w_lo, w0, w1); unpack2(w_hi, w2, w3);
            ull wp0 = pack2(fmaxf(w0,0.f), fmaxf(w0,0.f));
            ull wp1 = pack2(fmaxf(w1,0.f), fmaxf(w1,0.f));
            ull wp2_ = pack2(fmaxf(w2,0.f), fmaxf(w2,0.f));
            ull wp3 = pack2(fmaxf(w3,0.f), fmaxf(w3,0.f));
            a0B = fmul2(wp0, Wr[0][0]); a1B = fmul2(wp0, Wr[0][1]);
            a2B = fmul2(wp0, Wr[0][2]); a3B = fmul2(wp0, Wr[0][3]);
            a0B = ffma2(wp1, Wr[1][0], a0B); a1B = ffma2(wp1, Wr[1][1], a1B);
            a2B = ffma2(wp1, Wr[1][2], a2B); a3B = ffma2(wp1, Wr[1][3], a3B);
            a0B = ffma2(wp2_, Wr[2][0], a0B); a1B = ffma2(wp2_, Wr[2][1], a1B);
            a2B = ffma2(wp2_, Wr[2][2], a2B); a3B = ffma2(wp2_, Wr[2][3], a3B);
            a0B = ffma2(wp3, Wr[3][0], a0B); a1B = ffma2(wp3, Wr[3][1], a1B);
            a2B = ffma2(wp3, Wr[3][2], a2B); a3B = ffma2(wp3, Wr[3][3], a3B);
        }

        // ---- interleaved butterflies ----
        ull tA2 = __shfl_xor_sync(0xffffffffu, a2A, 8);
        ull tB2 = __shfl_xor_sync(0xffffffffu, a2B, 8);
        ull tA3 = __shfl_xor_sync(0xffffffffu, a3A, 8);
        ull tB3 = __shfl_xor_sync(0xffffffffu, a3B, 8);
        a0A = fadd2(a0A, tA2); a0B = fadd2(a0B, tB2);
        a1A = fadd2(a1A, tA3); a1B = fadd2(a1B, tB3);
        ull uA = __shfl_xor_sync(0xffffffffu, a1A, 4);
        ull uB = __shfl_xor_sync(0xffffffffu, a1B, 4);
        a0A = fadd2(a0A, uA); a0B = fadd2(a0B, uB);
        uA = __shfl_xor_sync(0xffffffffu, a0A, 2);
        uB = __shfl_xor_sync(0xffffffffu, a0B, 2);
        a0A = fadd2(a0A, uA); a0B = fadd2(a0B, uB);
        uA = __shfl_xor_sync(0xffffffffu, a0A, 1);
        uB = __shfl_xor_sync(0xffffffffu, a0B, 1);
        a0A = fadd2(fadd2(a0A, uA), biasu);
        a0B = fadd2(fadd2(a0B, uB), biasu);

        if ((lane & 3) == 0) {
            *((ull*)g_w1 + (size_t)pr_0*4 + P) = a0A;
            *((ull*)g_w1 + (size_t)pr_1*4 + P) = a0B;
        }

        stS = fadd2(stS, fadd2(a0A, a0B));
        stQ = ffma2(a0A, a0A, stQ);
        stQ = ffma2(a0B, a0B, stQ);
    }

    stS = fadd2(stS, __shfl_xor_sync(0xffffffffu, stS, 16));
    stQ = fadd2(stQ, __shfl_xor_sync(0xffffffffu, stQ, 16));
    if (lane < 16 && (lane & 3) == 0) {
        float s0, s1, q0, q1;
        unpack2(stS, s0, s1); unpack2(stQ, q0, q1);
        wred[wrp*16 + 2*P]     = s0;
        wred[wrp*16 + 2*P + 1] = s1;
        wred[wrp*16 + 8 + 2*P]     = q0;
        wred[wrp*16 + 8 + 2*P + 1] = q1;
    }
    __syncthreads();
    if (tid < 16) {
        float s = 0.f;
        #pragma unroll
        for (int w = 0; w < 8; w++) s += wred[w*16 + tid];
        atomicAdd(&g_accU[tid], s);
    }
}

// ---------------- K4: bn2+relu -> @Ww2 -> softmax(ns) -> aggregate ----------------
__global__ void __launch_bounds__(256) k4(
                   const int* __restrict__ idx,
                   const float* __restrict__ Wp2, const float* __restrict__ bp2,
                   const float* __restrict__ gw2, const float* __restrict__ bw2bn,
                   const float* __restrict__ Ww2, const float* __restrict__ bw2,
                   float* __restrict__ out)
{
    __shared__ float w1s[4][128];
    __shared__ float hs[4][128];
    __shared__ float w2s[4][128];
    __shared__ float prs[4][48];
    __shared__ int   gix4[4][16];    // g*64
    __shared__ float wp2s[192], bp2s[64], wws[64], bws[8];
    int tid = threadIdx.x;
    int sub = tid >> 6, ct = tid & 63;
    int n = blockIdx.x*4 + sub;

    for (int i = tid; i < 192; i += 256) wp2s[i] = Wp2[i];
    if (tid < 64) { bp2s[tid] = bp2[tid]; wws[tid] = Ww2[tid]; }
    if (tid < 8)  bws[tid] = bw2[tid];

    w1s[sub][ct]      = g_w1[n*128 + ct];
    w1s[sub][ct + 64] = g_w1[n*128 + ct + 64];
    if (ct < 16) {
        gix4[sub][ct] = idx[n*16 + ct] << 6;
        float4 h = g_prh4[n*16 + ct];
        prs[sub][ct] = h.x; prs[sub][16 + ct] = h.y; prs[sub][32 + ct] = h.z;
    }

    int u = ct & 7;
    float mean = g_accU[u] / MF;
    float var  = g_accU[8 + u] / MF - mean*mean;
    float sc2  = gw2[u] * rsqrtf(var + EPS);
    float sh2  = bw2bn[u] - mean*sc2;
    __syncthreads();

    hs[sub][ct]      = fmaxf(w1s[sub][ct]*sc2 + sh2, 0.f);
    hs[sub][ct + 64] = fmaxf(w1s[sub][ct + 64]*sc2 + sh2, 0.f);
    __syncthreads();

    #pragma unroll
    for (int o = ct; o < 128; o += 64) {
        int j = o >> 3, t = o & 7;
        float v = bws[t];
        #pragma unroll
        for (int uu = 0; uu < 8; uu++) v += hs[sub][j*8 + uu] * wws[uu*8 + t];
        w2s[sub][o] = v;
    }
    __syncthreads();

    if (ct < 8) {
        int t = ct;
        float m = -1e30f;
        #pragma unroll
        for (int j = 0; j < 16; j++) m = fmaxf(m, w2s[sub][j*8 + t]);
        float e[16], ssum = 0.f;
        #pragma unroll
        for (int j = 0; j < 16; j++) { e[j] = __expf(w2s[sub][j*8 + t] - m); ssum += e[j]; }
        float inv = 1.f / ssum;
        #pragma unroll
        for (int j = 0; j < 16; j++) w2s[sub][j*8 + t] = e[j] * inv;
    }
    __syncthreads();

    int t = ct & 7;
    float a0 = wp2s[ct], a1 = wp2s[64 + ct], a2 = wp2s[128 + ct], bb = bp2s[ct];
    float acc = 0.f;
    #pragma unroll
    for (int j = 0; j < 16; j++) {
        int goff = gix4[sub][j];
        float v = __ldg(&g_xv[goff + ct]);
        float pr = fmaf(prs[sub][32 + j], a2, fmaf(prs[sub][16 + j], a1, fmaf(prs[sub][j], a0, bb)));
        acc += (v + pr) * w2s[sub][j*8 + t];
    }
    out[n*64 + ct] = acc;
}

// ---------------- launch ----------------
extern "C" void kernel_launch(void* const* d_in, const int* in_sizes, int n_in,
                              void* d_out, int out_size)
{
    const float* p    = (const float*)d_in[0];
    const float* x    = (const float*)d_in[1];
    const int*   idx  = (const int*)d_in[2];
    const float* Wq   = (const float*)d_in[3];
    const float* bq   = (const float*)d_in[4];
    const float* Wk   = (const float*)d_in[5];
    const float* bk   = (const float*)d_in[6];
    const float* Wv   = (const float*)d_in[7];
    const float* bv   = (const float*)d_in[8];
    const float* Wp1  = (const float*)d_in[9];
    const float* bp1  = (const float*)d_in[10];
    const float* gp   = (const float*)d_in[11];
    const float* bpbn = (const float*)d_in[12];
    const float* Wp2  = (const float*)d_in[13];
    const float* bp2  = (const float*)d_in[14];
    const float* gw1  = (const float*)d_in[15];
    const float* bw1bn= (const float*)d_in[16];
    const float* Ww1  = (const float*)d_in[17];
    const float* bw1  = (const float*)d_in[18];
    const float* gw2  = (const float*)d_in[19];
    const float* bw2bn= (const float*)d_in[20];
    const float* Ww2  = (const float*)d_in[21];
    const float* bw2  = (const float*)d_in[22];
    float* out = (float*)d_out;

    size_t smem1 = (size_t)(64*48*4 + 64*68 + 48*4) * 4;  // ~66KB
    cudaFuncSetAttribute(k1, cudaFuncAttributeMaxDynamicSharedMemorySize, (int)smem1);

    k_zero<<<1, 256>>>();
    k1<<<1024, 256, smem1>>>(x, p, idx, Wq, bq, Wk, bk, Wv, bv, Wp1, bp1);
    k2<<<1024, 256>>>(p, idx, Wp1, bp1, gp, bpbn, Wp2, bp2);
    k3<<<2048, 256>>>(idx, Wp2, bp2, gw1, bw1bn, Ww1, bw1);
    k4<<<16384, 256>>>(idx, Wp2, bp2, gw2, bw2bn, Ww2, bw2, out);
}

// round 10
// speedup vs baseline: 1.0395x; 1.0092x over previous
#include <cuda_runtime.h>

#define NPTS 65536
#define NS 16
#define NPAIR (NPTS*NS)
#define MF 1048576.0f
#define EPS 1e-5f

typedef unsigned long long ull;

__device__ __forceinline__ ull ffma2(ull a, ull b, ull c) {
    ull d; asm("fma.rn.f32x2 %0,%1,%2,%3;" : "=l"(d) : "l"(a), "l"(b), "l"(c)); return d;
}
__device__ __forceinline__ ull fmul2(ull a, ull b) {
    ull d; asm("mul.rn.f32x2 %0,%1,%2;" : "=l"(d) : "l"(a), "l"(b)); return d;
}
__device__ __forceinline__ ull fadd2(ull a, ull b) {
    ull d; asm("add.rn.f32x2 %0,%1,%2;" : "=l"(d) : "l"(a), "l"(b)); return d;
}
__device__ __forceinline__ ull pack2(float lo, float hi) {
    ull d; asm("mov.b64 %0,{%1,%2};" : "=l"(d) : "f"(lo), "f"(hi)); return d;
}
__device__ __forceinline__ void unpack2(ull v, float& lo, float& hi) {
    asm("mov.b64 {%0,%1},%2;" : "=f"(lo), "=f"(hi) : "l"(v));
}

// ---------------- scratch ----------------
__device__ float  g_xq[NPTS*64];
__device__ float  g_xk[NPTS*64];
__device__ float  g_xv[NPTS*64];
__device__ float4 g_pr1r[NPAIR];   // raw pr1 {v0,v1,v2,0} per pair (from k1)
__device__ float4 g_prh4[NPAIR];   // {h0,h1,h2,0} per pair (post BN+relu)
__device__ float  g_w1[NPAIR*8];
__device__ float  g_accP[6];
__device__ float  g_accW[128];
__device__ float  g_accU[16];

__global__ void k_zero() {
    int t = threadIdx.x;
    if (t < 6)   g_accP[t] = 0.f;
    if (t < 128) g_accW[t] = 0.f;
    if (t < 16)  g_accU[t] = 0.f;
}

// ---------------- K1: qkv GEMM (64 pts/block) + pr1 raw store + BN-P stats ----------------
__global__ void __launch_bounds__(256) k1(
                   const float* __restrict__ x, const float* __restrict__ p,
                   const int* __restrict__ idx,
                   const float* __restrict__ Wq, const float* __restrict__ bq,
                   const float* __restrict__ Wk, const float* __restrict__ bk,
                   const float* __restrict__ Wv, const float* __restrict__ bv,
                   const float* __restrict__ Wp1, const float* __restrict__ bp1)
{
    extern __shared__ float sm[];
    float4* ws4  = (float4*)sm;            // [64][48] float4
    float*  xs   = sm + 64*48*4;           // [64][68]
    float4* bsm4 = (float4*)(xs + 64*68);  // [48]
    int tid = threadIdx.x;
    int base = blockIdx.x * 64;

    for (int i = tid; i < 64*48; i += 256) {
        int k = i / 48, r = i - k*48;
        int seg = r >> 4, tx = r & 15;
        const float4* src = (seg == 0) ? (const float4*)Wq :
                            (seg == 1) ? (const float4*)Wk : (const float4*)Wv;
        ws4[i] = src[k*16 + tx];
    }
    {
        float4* xs4 = (float4*)xs;
        for (int i = tid; i < 64*16; i += 256) {
            int pt = i >> 4, kk = i & 15;
            xs4[pt*17 + kk] = ((const float4*)x)[(base + pt)*16 + kk];
        }
    }
    if (tid < 48) {
        int seg = tid >> 4, tx = tid & 15;
        const float4* src = (seg == 0) ? (const float4*)bq :
                            (seg == 1) ? (const float4*)bk : (const float4*)bv;
        bsm4[tid] = src[tx];
    }
    __syncthreads();

    int tx = tid & 15, ty = tid >> 4;
    ulonglong2 acc[3][4];
    #pragma unroll
    for (int s = 0; s < 3; s++) {
        ulonglong2 b = ((ulonglong2*)bsm4)[s*16 + tx];
        #pragma unroll
        for (int r = 0; r < 4; r++) acc[s][r] = b;
    }

    #pragma unroll 4
    for (int kq = 0; kq < 16; kq++) {
        float4 aq[4];
        #pragma unroll
        for (int r = 0; r < 4; r++) aq[r] = *(float4*)&xs[(ty*4 + r)*68 + kq*4];
        #pragma unroll
        for (int e = 0; e < 4; e++) {
            int k = kq*4 + e;
            ull ap[4];
            #pragma unroll
            for (int r = 0; r < 4; r++) {
                float av = ((float*)&aq[r])[e];
                ap[r] = pack2(av, av);
            }
            #pragma unroll
            for (int s = 0; s < 3; s++) {
                ulonglong2 w2 = *(ulonglong2*)&ws4[k*48 + s*16 + tx];
                #pragma unroll
                for (int r = 0; r < 4; r++) {
                    acc[s][r].x = ffma2(ap[r], w2.x, acc[s][r].x);
                    acc[s][r].y = ffma2(ap[r], w2.y, acc[s][r].y);
                }
            }
        }
    }

    #pragma unroll
    for (int r = 0; r < 4; r++) {
        int pt = base + ty*4 + r;
        ((ulonglong2*)&g_xq[pt*64])[tx] = acc[0][r];
        ((ulonglong2*)&g_xk[pt*64])[tx] = acc[1][r];
        ((ulonglong2*)&g_xv[pt*64])[tx] = acc[2][r];
    }

    // ---- pr1 raw compute + store + stats over this block's 1024 pairs ----
    float w00 = Wp1[0], w01 = Wp1[1], w02 = Wp1[2];
    float w10 = Wp1[3], w11 = Wp1[4], w12 = Wp1[5];
    float w20 = Wp1[6], w21 = Wp1[7], w22 = Wp1[8];
    float c0 = bp1[0], c1 = bp1[1], c2 = bp1[2];
    float s0=0,s1=0,s2=0,q0=0,q1=0,q2=0;
    for (int t = tid; t < 1024; t += 256) {
        int n = base + (t >> 4);
        int g = idx[n*NS + (t & 15)];
        float r0 = p[g*3+0] - p[n*3+0];
        float r1 = p[g*3+1] - p[n*3+1];
        float r2 = p[g*3+2] - p[n*3+2];
        float v0 = c0 + r0*w00 + r1*w10 + r2*w20;
        float v1 = c1 + r0*w01 + r1*w11 + r2*w21;
        float v2 = c2 + r0*w02 + r1*w12 + r2*w22;
        g_pr1r[base*NS + t] = make_float4(v0, v1, v2, 0.f);
        s0 += v0; s1 += v1; s2 += v2;
        q0 += v0*v0; q1 += v1*v1; q2 += v2*v2;
    }
    #pragma unroll
    for (int off = 16; off; off >>= 1) {
        s0 += __shfl_xor_sync(0xffffffffu, s0, off);
        s1 += __shfl_xor_sync(0xffffffffu, s1, off);
        s2 += __shfl_xor_sync(0xffffffffu, s2, off);
        q0 += __shfl_xor_sync(0xffffffffu, q0, off);
        q1 += __shfl_xor_sync(0xffffffffu, q1, off);
        q2 += __shfl_xor_sync(0xffffffffu, q2, off);
    }
    __syncthreads();
    float* red = sm;
    int lane = tid & 31, wrp = tid >> 5;
    if (lane == 0) {
        red[wrp*6+0] = s0; red[wrp*6+1] = s1; red[wrp*6+2] = s2;
        red[wrp*6+3] = q0; red[wrp*6+4] = q1; red[wrp*6+5] = q2;
    }
    __syncthreads();
    if (tid < 6) {
        float t2 = 0.f;
        #pragma unroll
        for (int w = 0; w < 8; w++) t2 += red[w*6 + tid];
        atomicAdd(&g_accP[tid], t2);
    }
}

// ---------------- K2: streaming BN-P + w-channel BN stats ----------------
__global__ void __launch_bounds__(256) k2(
                   const int* __restrict__ idx,
                   const float* __restrict__ gp, const float* __restrict__ bpbn,
                   const float* __restrict__ Wp2, const float* __restrict__ bp2)
{
    __shared__ float4 prh4[1024];
    __shared__ float  xqn[64*64];
    __shared__ int    goff[1024];    // g*16 = float4-row offset
    __shared__ float  sred[1024];
    int tid = threadIdx.x;
    int pair0 = blockIdx.x * 1024;
    int pbase = pair0 >> 4;

    for (int i = tid; i < 1024; i += 256) goff[i] = idx[pair0 + i] << 4;
    for (int i = tid; i < 4096; i += 256) xqn[i] = -g_xq[pbase*64 + i];

    float scP[3], shP[3];
    #pragma unroll
    for (int c = 0; c < 3; c++) {
        float mean = g_accP[c] / MF;
        float var  = g_accP[3+c] / MF - mean*mean;
        float sc   = gp[c] * rsqrtf(var + EPS);
        scP[c] = sc;
        shP[c] = bpbn[c] - mean*sc;
    }
    __syncthreads();

    // phase A: streaming read raw pr1 -> BN+relu -> smem + gmem
    #pragma unroll
    for (int kk = 0; kk < 4; kk++) {
        int t = tid + kk*256;
        float4 v = __ldg(&g_pr1r[pair0 + t]);
        float h0 = fmaxf(v.x*scP[0] + shP[0], 0.f);
        float h1 = fmaxf(v.y*scP[1] + shP[1], 0.f);
        float h2 = fmaxf(v.z*scP[2] + shP[2], 0.f);
        float4 h = make_float4(h0, h1, h2, 0.f);
        prh4[t] = h;
        g_prh4[pair0 + t] = h;
    }
    __syncthreads();

    // phase B: w stats, 2-way interleaved
    int cq = (tid & 15) * 4;
    int lof = tid & 15;
    float4 A0q = __ldg((const float4*)&Wp2[cq]);
    float4 A1q = __ldg((const float4*)&Wp2[64 + cq]);
    float4 A2q = __ldg((const float4*)&Wp2[128 + cq]);
    float4 Bq  = __ldg((const float4*)&bp2[cq]);
    ulonglong2 A0u = *(ulonglong2*)&A0q, A1u = *(ulonglong2*)&A1q;
    ulonglong2 A2u = *(ulonglong2*)&A2q, Bu  = *(ulonglong2*)&Bq;

    ull s_lo = 0, s_hi = 0, ss_lo = 0, ss_hi = 0;
    int pl = tid >> 4;
    #pragma unroll 1
    for (int k = 0; k < 64; k += 2) {
        int t0 = pl + 16*k;
        int t1 = t0 + 16;
        float4 xkq0 = __ldg((const float4*)g_xk + goff[t0] + lof);
        float4 xkq1 = __ldg((const float4*)g_xk + goff[t1] + lof);
        float4 h40 = prh4[t0];
        float4 h41 = prh4[t1];
        ulonglong2 xqu0 = *(ulonglong2*)&xqn[(t0 >> 4)*64 + cq];
        ulonglong2 xqu1 = *(ulonglong2*)&xqn[(t1 >> 4)*64 + cq];
        {
            ull h0p = pack2(h40.x, h40.x), h1p = pack2(h40.y, h40.y), h2p = pack2(h40.z, h40.z);
            ulonglong2 xku = *(ulonglong2*)&xkq0;
            ull t_lo = ffma2(h2p, A2u.x, ffma2(h1p, A1u.x, ffma2(h0p, A0u.x, Bu.x)));
            ull t_hi = ffma2(h2p, A2u.y, ffma2(h1p, A1u.y, ffma2(h0p, A0u.y, Bu.y)));
            ull w_lo = fadd2(xku.x, fadd2(xqu0.x, t_lo));
            ull w_hi = fadd2(xku.y, fadd2(xqu0.y, t_hi));
            s_lo = fadd2(s_lo, w_lo); s_hi = fadd2(s_hi, w_hi);
            ss_lo = ffma2(w_lo, w_lo, ss_lo); ss_hi = ffma2(w_hi, w_hi, ss_hi);
        }
        {
            ull h0p = pack2(h41.x, h41.x), h1p = pack2(h41.y, h41.y), h2p = pack2(h41.z, h41.z);
            ulonglong2 xku = *(ulonglong2*)&xkq1;
            ull t_lo = ffma2(h2p, A2u.x, ffma2(h1p, A1u.x, ffma2(h0p, A0u.x, Bu.x)));
            ull t_hi = ffma2(h2p, A2u.y, ffma2(h1p, A1u.y, ffma2(h0p, A0u.y, Bu.y)));
            ull w_lo = fadd2(xku.x, fadd2(xqu1.x, t_lo));
            ull w_hi = fadd2(xku.y, fadd2(xqu1.y, t_hi));
            s_lo = fadd2(s_lo, w_lo); s_hi = fadd2(s_hi, w_hi);
            ss_lo = ffma2(w_lo, w_lo, ss_lo); ss_hi = ffma2(w_hi, w_hi, ss_hi);
        }
    }

    float v[8];
    unpack2(s_lo, v[0], v[1]); unpack2(s_hi, v[2], v[3]);
    unpack2(ss_lo, v[4], v[5]); unpack2(ss_hi, v[6], v[7]);
    #pragma unroll
    for (int i = 0; i < 8; i++) v[i] += __shfl_xor_sync(0xffffffffu, v[i], 16);
    int lane = tid & 31, wrp = tid >> 5;
    if (lane < 16) {
        #pragma unroll
        for (int i = 0; i < 8; i++) sred[lane*64 + wrp*8 + i] = v[i];
    }
    __syncthreads();
    if (tid < 128) {
        int q = tid >> 3, vi = tid & 7;
        float s = 0.f;
        #pragma unroll
        for (int w = 0; w < 8; w++) s += sred[q*64 + w*8 + vi];
        int gi = (vi < 4) ? (q*4 + vi) : (64 + q*4 + vi - 4);
        atomicAdd(&g_accW[gi], s);
    }
}

// ---------------- K3: 16 lanes/pair, reg tables, 2-way interleaved + goff ----------------
__global__ void __launch_bounds__(256, 2) k3(
                   const int* __restrict__ idx,
                   const float* __restrict__ Wp2, const float* __restrict__ bp2,
                   const float* __restrict__ gw1, const float* __restrict__ bw1bn,
                   const float* __restrict__ Ww1, const float* __restrict__ bw1)
{
    __shared__ float xqn[32*64];     // -xq * sc
    __shared__ int   gixs[512];      // g*16 (ulonglong2-row offset)
    __shared__ float sS[64];
    __shared__ float wred[8*16];
    int tid = threadIdx.x;
    int lane = tid & 31, wrp = tid >> 5;
    int pair0 = blockIdx.x * 512;
    int pbase = pair0 >> 4;
    int cq = (tid & 15) * 4;
    int lof = tid & 15;
    int slot = tid >> 4;
    int P = (lane >> 2) & 3;

    if (tid < 64) {
        int c = tid;
        float mean = g_accW[c] / MF;
        float var  = g_accW[64 + c] / MF - mean*mean;
        sS[c] = gw1[c] * rsqrtf(var + EPS);
    }
    for (int i = tid; i < 512; i += 256) gixs[i] = idx[pair0 + i] << 4;

    ull A0u[2], A1u[2], A2u[2], Bu[2], Su[2];
    {
        float a0[4], a1[4], a2[4], bb[4], sv[4];
        #pragma unroll
        for (int e = 0; e < 4; e++) {
            int c = cq + e;
            float mean = g_accW[c] / MF;
            float var  = g_accW[64 + c] / MF - mean*mean;
            float sc   = gw1[c] * rsqrtf(var + EPS);
            float sh   = bw1bn[c] - mean*sc;
            sv[e] = sc;
            a0[e] = Wp2[c]*sc; a1[e] = Wp2[64+c]*sc; a2[e] = Wp2[128+c]*sc;
            bb[e] = bp2[c]*sc + sh;
        }
        A0u[0] = pack2(a0[0], a0[1]); A0u[1] = pack2(a0[2], a0[3]);
        A1u[0] = pack2(a1[0], a1[1]); A1u[1] = pack2(a1[2], a1[3]);
        A2u[0] = pack2(a2[0], a2[1]); A2u[1] = pack2(a2[2], a2[3]);
        Bu[0]  = pack2(bb[0], bb[1]); Bu[1]  = pack2(bb[2], bb[3]);
        Su[0]  = pack2(sv[0], sv[1]); Su[1]  = pack2(sv[2], sv[3]);
    }

    ull Wr[4][4];
    #pragma unroll
    for (int e = 0; e < 4; e++)
        #pragma unroll
        for (int s = 0; s < 4; s++)
            Wr[e][s] = __ldg((const ull*)Ww1 + (cq + e)*4 + (P ^ s));
    ull biasu = __ldg((const ull*)bw1 + P);
    __syncthreads();

    for (int i = tid; i < 2048; i += 256)
        xqn[i] = -g_xq[(size_t)pbase*64 + i] * sS[i & 63];
    __syncthreads();

    const ulonglong2* xkb = (const ulonglong2*)g_xk;
    ull stS = 0, stQ = 0;

    #pragma unroll 1
    for (int k = 0; k < 32; k += 2) {
        int li0 = slot + (k << 4);
        int li1 = li0 + 16;
        int pr_0 = pair0 + li0, pr_1 = pair0 + li1;
        float4 hA = __ldg(&g_prh4[pr_0]);
        float4 hB = __ldg(&g_prh4[pr_1]);
        ulonglong2 xkA = __ldg(xkb + gixs[li0] + lof);
        ulonglong2 xkB = __ldg(xkb + gixs[li1] + lof);
        ulonglong2 xqA = *(const ulonglong2*)&xqn[(k << 6) + cq];
        ulonglong2 xqB = *(const ulonglong2*)&xqn[((k + 1) << 6) + cq];

        ull a0A, a1A, a2A, a3A;
        {
            ull h0p = pack2(hA.x, hA.x), h1p = pack2(hA.y, hA.y), h2p = pack2(hA.z, hA.z);
            ull r_lo = ffma2(h2p, A2u[0], ffma2(h1p, A1u[0], ffma2(h0p, A0u[0], Bu[0])));
            ull r_hi = ffma2(h2p, A2u[1], ffma2(h1p, A1u[1], ffma2(h0p, A0u[1], Bu[1])));
            ull w_lo = ffma2(xkA.x, Su[0], fadd2(xqA.x, r_lo));
            ull w_hi = ffma2(xkA.y, Su[1], fadd2(xqA.y, r_hi));
            float w0, w1, w2, w3;
            unpack2(w_lo, w0, w1); unpack2(w_hi, w2, w3);
            ull wp0 = pack2(fmaxf(w0,0.f), fmaxf(w0,0.f));
            ull wp1 = pack2(fmaxf(w1,0.f), fmaxf(w1,0.f));
            ull wp2_ = pack2(fmaxf(w2,0.f), fmaxf(w2,0.f));
            ull wp3 = pack2(fmaxf(w3,0.f), fmaxf(w3,0.f));
            a0A = fmul2(wp0, Wr[0][0]); a1A = fmul2(wp0, Wr[0][1]);
            a2A = fmul2(wp0, Wr[0][2]); a3A = fmul2(wp0, Wr[0][3]);
            a0A = ffma2(wp1, Wr[1][0], a0A); a1A = ffma2(wp1, Wr[1][1], a1A);
            a2A = ffma2(wp1, Wr[1][2], a2A); a3A = ffma2(wp1, Wr[1][3], a3A);
            a0A = ffma2(wp2_, Wr[2][0], a0A); a1A = ffma2(wp2_, Wr[2][1], a1A);
            a2A = ffma2(wp2_, Wr[2][2], a2A); a3A = ffma2(wp2_, Wr[2][3], a3A);
            a0A = ffma2(wp3, Wr[3][0], a0A); a1A = ffma2(wp3, Wr[3][1], a1A);
            a2A = ffma2(wp3, Wr[3][2], a2A); a3A = ffma2(wp3, Wr[3][3], a3A);
        }
        ull a0B, a1B, a2B, a3B;
        {
            ull h0p = pack2(hB.x, hB.x), h1p = pack2(hB.y, hB.y), h2p = pack2(hB.z, hB.z);
            ull r_lo = ffma2(h2p, A2u[0], ffma2(h1p, A1u[0], ffma2(h0p, A0u[0], Bu[0])));
            ull r_hi = ffma2(h2p, A2u[1], ffma2(h1p, A1u[1], ffma2(h0p, A0u[1], Bu[1])));
            ull w_lo = ffma2(xkB.x, Su[0], fadd2(xqB.x, r_lo));
            ull w_hi = ffma2(xkB.y, Su[1], fadd2(xqB.y, r_hi));
            float w0, w1, w2, w3;
            unpack2(w_lo, w0, w1); unpack2(w_hi, w2, w3);
            ull wp0 = pack2(fmaxf(w0,0.f), fmaxf(w0,0.f));
            ull wp1 = pack2(fmaxf(w1,0.f), fmaxf(w1,0.f));
            ull wp2_ = pack2(fmaxf(w2,0.f), fmaxf(w2,0.f));
            ull wp3 = pack2(fmaxf(w3,0.f), fmaxf(w3,0.f));
            a0B = fmul2(wp0, Wr[0][0]); a1B = fmul2(wp0, Wr[0][1]);
            a2B = fmul2(wp0, Wr[0][2]); a3B = fmul2(wp0, Wr[0][3]);
            a0B = ffma2(wp1, Wr[1][0], a0B); a1B = ffma2(wp1, Wr[1][1], a1B);
            a2B = ffma2(wp1, Wr[1][2], a2B); a3B = ffma2(wp1, Wr[1][3], a3B);
            a0B = ffma2(wp2_, Wr[2][0], a0B); a1B = ffma2(wp2_, Wr[2][1], a1B);
            a2B = ffma2(wp2_, Wr[2][2], a2B); a3B = ffma2(wp2_, Wr[2][3], a3B);
            a0B = ffma2(wp3, Wr[3][0], a0B); a1B = ffma2(wp3, Wr[3][1], a1B);
            a2B = ffma2(wp3, Wr[3][2], a2B); a3B = ffma2(wp3, Wr[3][3], a3B);
        }

        ull tA2 = __shfl_xor_sync(0xffffffffu, a2A, 8);
        ull tB2 = __shfl_xor_sync(0xffffffffu, a2B, 8);
        ull tA3 = __shfl_xor_sync(0xffffffffu, a3A, 8);
        ull tB3 = __shfl_xor_sync(0xffffffffu, a3B, 8);
        a0A = fadd2(a0A, tA2); a0B = fadd2(a0B, tB2);
        a1A = fadd2(a1A, tA3); a1B = fadd2(a1B, tB3);
        ull uA = __shfl_xor_sync(0xffffffffu, a1A, 4);
        ull uB = __shfl_xor_sync(0xffffffffu, a1B, 4);
        a0A = fadd2(a0A, uA); a0B = fadd2(a0B, uB);
        uA = __shfl_xor_sync(0xffffffffu, a0A, 2);
        uB = __shfl_xor_sync(0xffffffffu, a0B, 2);
        a0A = fadd2(a0A, uA); a0B = fadd2(a0B, uB);
        uA = __shfl_xor_sync(0xffffffffu, a0A, 1);
        uB = __shfl_xor_sync(0xffffffffu, a0B, 1);
        a0A = fadd2(fadd2(a0A, uA), biasu);
        a0B = fadd2(fadd2(a0B, uB), biasu);

        if ((lane & 3) == 0) {
            *((ull*)g_w1 + (size_t)pr_0*4 + P) = a0A;
            *((ull*)g_w1 + (size_t)pr_1*4 + P) = a0B;
        }

        stS = fadd2(stS, fadd2(a0A, a0B));
        stQ = ffma2(a0A, a0A, stQ);
        stQ = ffma2(a0B, a0B, stQ);
    }

    stS = fadd2(stS, __shfl_xor_sync(0xffffffffu, stS, 16));
    stQ = fadd2(stQ, __shfl_xor_sync(0xffffffffu, stQ, 16));
    if (lane < 16 && (lane & 3) == 0) {
        float s0, s1, q0, q1;
        unpack2(stS, s0, s1); unpack2(stQ, q0, q1);
        wred[wrp*16 + 2*P]     = s0;
        wred[wrp*16 + 2*P + 1] = s1;
        wred[wrp*16 + 8 + 2*P]     = q0;
        wred[wrp*16 + 8 + 2*P + 1] = q1;
    }
    __syncthreads();
    if (tid < 16) {
        float s = 0.f;
        #pragma unroll
        for (int w = 0; w < 8; w++) s += wred[w*16 + tid];
        atomicAdd(&g_accU[tid], s);
    }
}

// ---------------- K4: bn2+relu -> @Ww2 -> softmax(ns) -> aggregate ----------------
__global__ void __launch_bounds__(256) k4(
                   const int* __restrict__ idx,
                   const float* __restrict__ Wp2, const float* __restrict__ bp2,
                   const float* __restrict__ gw2, const float* __restrict__ bw2bn,
                   const float* __restrict__ Ww2, const float* __restrict__ bw2,
                   float* __restrict__ out)
{
    __shared__ float w1s[4][128];
    __shared__ float hs[4][128];
    __shared__ float w2s[4][128];
    __shared__ float prs[4][48];
    __shared__ int   gix4[4][16];    // g*64
    __shared__ float wp2s[192], bp2s[64], wws[64], bws[8];
    int tid = threadIdx.x;
    int sub = tid >> 6, ct = tid & 63;
    int n = blockIdx.x*4 + sub;

    for (int i = tid; i < 192; i += 256) wp2s[i] = Wp2[i];
    if (tid < 64) { bp2s[tid] = bp2[tid]; wws[tid] = Ww2[tid]; }
    if (tid < 8)  bws[tid] = bw2[tid];

    w1s[sub][ct]      = g_w1[n*128 + ct];
    w1s[sub][ct + 64] = g_w1[n*128 + ct + 64];
    if (ct < 16) {
        gix4[sub][ct] = idx[n*16 + ct] << 6;
        float4 h = g_prh4[n*16 + ct];
        prs[sub][ct] = h.x; prs[sub][16 + ct] = h.y; prs[sub][32 + ct] = h.z;
    }

    int u = ct & 7;
    float mean = g_accU[u] / MF;
    float var  = g_accU[8 + u] / MF - mean*mean;
    float sc2  = gw2[u] * rsqrtf(var + EPS);
    float sh2  = bw2bn[u] - mean*sc2;
    __syncthreads();

    hs[sub][ct]      = fmaxf(w1s[sub][ct]*sc2 + sh2, 0.f);
    hs[sub][ct + 64] = fmaxf(w1s[sub][ct + 64]*sc2 + sh2, 0.f);
    __syncthreads();

    #pragma unroll
    for (int o = ct; o < 128; o += 64) {
        int j = o >> 3, t = o & 7;
        float v = bws[t];
        #pragma unroll
        for (int uu = 0; uu < 8; uu++) v += hs[sub][j*8 + uu] * wws[uu*8 + t];
        w2s[sub][o] = v;
    }
    __syncthreads();

    if (ct < 8) {
        int t = ct;
        float m = -1e30f;
        #pragma unroll
        for (int j = 0; j < 16; j++) m = fmaxf(m, w2s[sub][j*8 + t]);
        float e[16], ssum = 0.f;
        #pragma unroll
        for (int j = 0; j < 16; j++) { e[j] = __expf(w2s[sub][j*8 + t] - m); ssum += e[j]; }
        float inv = 1.f / ssum;
        #pragma unroll
        for (int j = 0; j < 16; j++) w2s[sub][j*8 + t] = e[j] * inv;
    }
    __syncthreads();

    int t = ct & 7;
    float a0 = wp2s[ct], a1 = wp2s[64 + ct], a2 = wp2s[128 + ct], bb = bp2s[ct];
    float acc = 0.f;
    #pragma unroll
    for (int j = 0; j < 16; j++) {
        int goff = gix4[sub][j];
        float v = __ldg(&g_xv[goff + ct]);
        float pr = fmaf(prs[sub][32 + j], a2, fmaf(prs[sub][16 + j], a1, fmaf(prs[sub][j], a0, bb)));
        acc += (v + pr) * w2s[sub][j*8 + t];
    }
    out[n*64 + ct] = acc;
}

// ---------------- launch ----------------
extern "C" void kernel_launch(void* const* d_in, const int* in_sizes, int n_in,
                              void* d_out, int out_size)
{
    const float* p    = (const float*)d_in[0];
    const float* x    = (const float*)d_in[1];
    const int*   idx  = (const int*)d_in[2];
    const float* Wq   = (const float*)d_in[3];
    const float* bq   = (const float*)d_in[4];
    const float* Wk   = (const float*)d_in[5];
    const float* bk   = (const float*)d_in[6];
    const float* Wv   = (const float*)d_in[7];
    const float* bv   = (const float*)d_in[8];
    const float* Wp1  = (const float*)d_in[9];
    const float* bp1  = (const float*)d_in[10];
    const float* gp   = (const float*)d_in[11];
    const float* bpbn = (const float*)d_in[12];
    const float* Wp2  = (const float*)d_in[13];
    const float* bp2  = (const float*)d_in[14];
    const float* gw1  = (const float*)d_in[15];
    const float* bw1bn= (const float*)d_in[16];
    const float* Ww1  = (const float*)d_in[17];
    const float* bw1  = (const float*)d_in[18];
    const float* gw2  = (const float*)d_in[19];
    const float* bw2bn= (const float*)d_in[20];
    const float* Ww2  = (const float*)d_in[21];
    const float* bw2  = (const float*)d_in[22];
    float* out = (float*)d_out;

    size_t smem1 = (size_t)(64*48*4 + 64*68 + 48*4) * 4;  // ~66KB
    cudaFuncSetAttribute(k1, cudaFuncAttributeMaxDynamicSharedMemorySize, (int)smem1);

    k_zero<<<1, 256>>>();
    k1<<<1024, 256, smem1>>>(x, p, idx, Wq, bq, Wk, bk, Wv, bv, Wp1, bp1);
    k2<<<1024, 256>>>(idx, gp, bpbn, Wp2, bp2);
    k3<<<2048, 256>>>(idx, Wp2, bp2, gw1, bw1bn, Ww1, bw1);
    k4<<<16384, 256>>>(idx, Wp2, bp2, gw2, bw2bn, Ww2, bw2, out);
}